// round 1
// baseline (speedup 1.0000x reference)
#include <cuda_runtime.h>
#include <cstddef>

// ---------------------------------------------------------------------------
// Conditional-DETR cross attention (first layer path).
// Shapes: query [900,4,256], key/value/key_pos [4096,4,256], H=8, d=32,
// concat head dim = 64, scale = 1/sqrt(64) = 0.125.
//
// Pipeline:
//  1. kp  = key_pos @ Wkp^T + bkp        -> Kcat[..][32:64]   (per-head scatter)
//  2. k   = key @ Wkc^T + bkc + kp       -> Kcat[..][0:32]
//  3. v   = value @ Wv^T + bv            -> Vh
//  4. q   = (query@Wqc^T + query_pos@Wqp^T + bqc + bqp)*scale -> Qcat[0:32]
//  5. qse = (qsine@Wqs^T + bqs)*scale    -> Qcat[32:64]
//  6. flash attention over Kcat/Vh       -> Oattn [900,4,256]
//  7. out = query + Oattn @ Wo^T + bo    -> d_out
// ---------------------------------------------------------------------------

#define NQ    900
#define NK    4096
#define BATCH 4
#define CDIM  256
#define NH    8
#define DV    32
#define DQK   64
#define QSCALE 0.125f

// scratch (device globals; no cudaMalloc allowed)
__device__ float g_Kcat[(size_t)32 * NK * DQK];   // [b*8+h][m][64]
__device__ float g_Vh[(size_t)32 * NK * DV];      // [b*8+h][m][32]
__device__ float g_Qcat[(size_t)32 * NQ * DQK];   // [b*8+h][n][64] (pre-scaled)
__device__ float g_Oattn[(size_t)NQ * BATCH * CDIM]; // [n][b][h*32+v]

#define M_KP  0
#define M_KC  1
#define M_V   2
#define M_Q   3
#define M_QS  4
#define M_OUT 5

// ---------------------------------------------------------------------------
// Generic tiled GEMM: out[row,col] = sum_e A[row,e] * W[col,e] + bias[col]
// Tile 64x64, BK=16, 256 threads, 4x4 per thread. MODE selects epilogue.
// MODE==M_Q additionally accumulates A2 @ W2^T + bias2 (K extended to 512).
// ---------------------------------------------------------------------------
template<int MODE>
__global__ __launch_bounds__(256)
void proj_kernel(const float* __restrict__ A, const float* __restrict__ W,
                 const float* __restrict__ bias,
                 const float* __restrict__ A2, const float* __restrict__ W2,
                 const float* __restrict__ bias2,
                 const float* __restrict__ addsrc,
                 float* __restrict__ outp, int M)
{
    __shared__ float As[16][68];
    __shared__ float Bs[16][68];

    const int tid = threadIdx.x;
    const int ty = tid >> 4, tx = tid & 15;
    const int m0 = blockIdx.x * 64;
    const int c0 = blockIdx.y * 64;

    const int lrow = tid >> 2;          // 0..63
    const int lk4  = (tid & 3) * 4;     // 0,4,8,12

    float acc[4][4] = {};

    const int nkt = (MODE == M_Q) ? 32 : 16;
    for (int kt = 0; kt < nkt; kt++) {
        const float* Ap = (MODE == M_OUT) ? g_Oattn : A;
        const float* Wp = W;
        int k0 = kt * 16;
        if (MODE == M_Q && kt >= 16) { Ap = A2; Wp = W2; k0 = (kt - 16) * 16; }

        float4 av = make_float4(0.f, 0.f, 0.f, 0.f);
        if (m0 + lrow < M)
            av = *(const float4*)&Ap[(size_t)(m0 + lrow) * CDIM + k0 + lk4];
        As[lk4 + 0][lrow] = av.x; As[lk4 + 1][lrow] = av.y;
        As[lk4 + 2][lrow] = av.z; As[lk4 + 3][lrow] = av.w;

        float4 wv = *(const float4*)&Wp[(size_t)(c0 + lrow) * CDIM + k0 + lk4];
        Bs[lk4 + 0][lrow] = wv.x; Bs[lk4 + 1][lrow] = wv.y;
        Bs[lk4 + 2][lrow] = wv.z; Bs[lk4 + 3][lrow] = wv.w;

        __syncthreads();
        #pragma unroll
        for (int k = 0; k < 16; k++) {
            float4 a = *(const float4*)&As[k][ty * 4];
            float4 b = *(const float4*)&Bs[k][tx * 4];
            acc[0][0] += a.x * b.x; acc[0][1] += a.x * b.y; acc[0][2] += a.x * b.z; acc[0][3] += a.x * b.w;
            acc[1][0] += a.y * b.x; acc[1][1] += a.y * b.y; acc[1][2] += a.y * b.z; acc[1][3] += a.y * b.w;
            acc[2][0] += a.z * b.x; acc[2][1] += a.z * b.y; acc[2][2] += a.z * b.z; acc[2][3] += a.z * b.w;
            acc[3][0] += a.w * b.x; acc[3][1] += a.w * b.y; acc[3][2] += a.w * b.z; acc[3][3] += a.w * b.w;
        }
        __syncthreads();
    }

    #pragma unroll
    for (int i = 0; i < 4; i++) {
        const int row = m0 + ty * 4 + i;
        if (row >= M) continue;
        #pragma unroll
        for (int j = 0; j < 4; j++) {
            const int col = c0 + tx * 4 + j;
            float val = acc[i][j] + bias[col];
            if (MODE == M_Q) val += bias2[col];

            if (MODE == M_KP) {
                const int m = row >> 2, b = row & 3, h = col >> 5, ii = col & 31;
                g_Kcat[((size_t)(b * NH + h) * NK + m) * DQK + 32 + ii] = val;
            } else if (MODE == M_KC) {
                const int m = row >> 2, b = row & 3, h = col >> 5, ii = col & 31;
                const size_t base = ((size_t)(b * NH + h) * NK + m) * DQK;
                g_Kcat[base + ii] = val + g_Kcat[base + 32 + ii];
            } else if (MODE == M_V) {
                const int m = row >> 2, b = row & 3, h = col >> 5, ii = col & 31;
                g_Vh[((size_t)(b * NH + h) * NK + m) * DV + ii] = val;
            } else if (MODE == M_Q) {
                const int n = row >> 2, b = row & 3, h = col >> 5, ii = col & 31;
                g_Qcat[((size_t)(b * NH + h) * NQ + n) * DQK + ii] = val * QSCALE;
            } else if (MODE == M_QS) {
                const int n = row >> 2, b = row & 3, h = col >> 5, ii = col & 31;
                g_Qcat[((size_t)(b * NH + h) * NQ + n) * DQK + 32 + ii] = val * QSCALE;
            } else { // M_OUT: residual add
                outp[(size_t)row * CDIM + col] = addsrc[(size_t)row * CDIM + col] + val;
            }
        }
    }
}

// ---------------------------------------------------------------------------
// Flash attention: grid (15 q-tiles, 32 bh). Block 256 threads.
// Q tile 64 queries, K tiles of 64 keys, online softmax, O in registers.
// ---------------------------------------------------------------------------
#define ATT_SMEM_FLOATS (3 * 64 * 68 + 64 * 32 + 3 * 64)

__global__ __launch_bounds__(256)
void attn_kernel()
{
    extern __shared__ float sm[];
    float* Qs = sm;               // [k=64][q stride 68]   (transposed)
    float* Ks = Qs + 64 * 68;     // [k=64][kc stride 68]  (transposed)
    float* Ss = Ks + 64 * 68;     // [q=64][kc stride 68]
    float* Vs = Ss + 64 * 68;     // [kc=64][32]
    float* mrow = Vs + 64 * 32;
    float* lrow = mrow + 64;
    float* alph = lrow + 64;

    const int tid = threadIdx.x;
    const int ty = tid >> 4, tx = tid & 15;
    const int bh = blockIdx.y;
    const int q0 = blockIdx.x * 64;

    // load Q tile (transposed) once
    #pragma unroll
    for (int t = 0; t < 4; t++) {
        int idx = tid + t * 256;      // 0..1023
        int q = idx >> 4;
        int k4 = (idx & 15) * 4;
        float4 v = make_float4(0.f, 0.f, 0.f, 0.f);
        int n = q0 + q;
        if (n < NQ) v = *(const float4*)&g_Qcat[((size_t)bh * NQ + n) * DQK + k4];
        Qs[(k4 + 0) * 68 + q] = v.x; Qs[(k4 + 1) * 68 + q] = v.y;
        Qs[(k4 + 2) * 68 + q] = v.z; Qs[(k4 + 3) * 68 + q] = v.w;
    }
    if (tid < 64) { mrow[tid] = -1e30f; lrow[tid] = 0.f; }

    float oacc[4][2] = {};

    for (int kt = 0; kt < NK / 64; kt++) {
        __syncthreads();   // previous PV phase done before overwriting smem
        const int mbase = kt * 64;

        #pragma unroll
        for (int t = 0; t < 4; t++) {
            int idx = tid + t * 256;
            int kc = idx >> 4;
            int k4 = (idx & 15) * 4;
            float4 v = *(const float4*)&g_Kcat[((size_t)bh * NK + mbase + kc) * DQK + k4];
            Ks[(k4 + 0) * 68 + kc] = v.x; Ks[(k4 + 1) * 68 + kc] = v.y;
            Ks[(k4 + 2) * 68 + kc] = v.z; Ks[(k4 + 3) * 68 + kc] = v.w;
        }
        #pragma unroll
        for (int t = 0; t < 2; t++) {
            int idx = tid + t * 256;  // 0..511
            int kc = idx >> 3;
            int v4 = (idx & 7) * 4;
            *(float4*)&Vs[kc * 32 + v4] =
                *(const float4*)&g_Vh[((size_t)bh * NK + mbase + kc) * DV + v4];
        }
        __syncthreads();

        // S = Q @ K^T   (4x4 per thread)
        float s[4][4] = {};
        #pragma unroll
        for (int k = 0; k < 64; k++) {
            float4 qv = *(const float4*)&Qs[k * 68 + ty * 4];
            float4 kv = *(const float4*)&Ks[k * 68 + tx * 4];
            s[0][0] += qv.x * kv.x; s[0][1] += qv.x * kv.y; s[0][2] += qv.x * kv.z; s[0][3] += qv.x * kv.w;
            s[1][0] += qv.y * kv.x; s[1][1] += qv.y * kv.y; s[1][2] += qv.y * kv.z; s[1][3] += qv.y * kv.w;
            s[2][0] += qv.z * kv.x; s[2][1] += qv.z * kv.y; s[2][2] += qv.z * kv.z; s[2][3] += qv.z * kv.w;
            s[3][0] += qv.w * kv.x; s[3][1] += qv.w * kv.y; s[3][2] += qv.w * kv.z; s[3][3] += qv.w * kv.w;
        }
        #pragma unroll
        for (int i = 0; i < 4; i++)
            *(float4*)&Ss[(ty * 4 + i) * 68 + tx * 4] =
                make_float4(s[i][0], s[i][1], s[i][2], s[i][3]);
        __syncthreads();

        // online softmax: thread -> (row = tid/4, 16-col chunk = (tid&3)*16)
        {
            const int r = tid >> 2;
            const int cc = (tid & 3) * 16;
            float mx = -1e30f;
            #pragma unroll
            for (int u = 0; u < 16; u++) mx = fmaxf(mx, Ss[r * 68 + cc + u]);
            mx = fmaxf(mx, __shfl_xor_sync(0xffffffffu, mx, 1));
            mx = fmaxf(mx, __shfl_xor_sync(0xffffffffu, mx, 2));
            const float mo = mrow[r];
            const float mn = fmaxf(mo, mx);
            float sum = 0.f;
            #pragma unroll
            for (int u = 0; u < 16; u++) {
                float p = __expf(Ss[r * 68 + cc + u] - mn);
                Ss[r * 68 + cc + u] = p;
                sum += p;
            }
            sum += __shfl_xor_sync(0xffffffffu, sum, 1);
            sum += __shfl_xor_sync(0xffffffffu, sum, 2);
            if ((tid & 3) == 0) {
                const float al = __expf(mo - mn);
                lrow[r] = lrow[r] * al + sum;
                mrow[r] = mn;
                alph[r] = al;
            }
        }
        __syncthreads();

        // O = O*alpha + P @ V   (4 rows x 2 cols per thread)
        #pragma unroll
        for (int i = 0; i < 4; i++) {
            const float al = alph[ty * 4 + i];
            oacc[i][0] *= al; oacc[i][1] *= al;
        }
        #pragma unroll
        for (int k = 0; k < 64; k++) {
            const float2 vv = *(const float2*)&Vs[k * 32 + tx * 2];
            #pragma unroll
            for (int i = 0; i < 4; i++) {
                const float p = Ss[(ty * 4 + i) * 68 + k];
                oacc[i][0] += p * vv.x;
                oacc[i][1] += p * vv.y;
            }
        }
    }

    // epilogue: normalize and scatter to [n][b][h*32+v]
    const int b = bh >> 3, h = bh & 7;
    #pragma unroll
    for (int i = 0; i < 4; i++) {
        const int n = q0 + ty * 4 + i;
        if (n >= NQ) continue;
        const float inv = 1.f / lrow[ty * 4 + i];
        const size_t base = ((size_t)n * BATCH + b) * CDIM + h * DV + tx * 2;
        g_Oattn[base + 0] = oacc[i][0] * inv;
        g_Oattn[base + 1] = oacc[i][1] * inv;
    }
}

// ---------------------------------------------------------------------------
extern "C" void kernel_launch(void* const* d_in, const int* in_sizes, int n_in,
                              void* d_out, int out_size)
{
    const float* query    = (const float*)d_in[0];
    const float* key      = (const float*)d_in[1];
    const float* value    = (const float*)d_in[2];
    const float* querypos = (const float*)d_in[3];
    const float* keypos   = (const float*)d_in[4];
    const float* qsine    = (const float*)d_in[5];
    const float* Wqc = (const float*)d_in[6];  const float* bqc = (const float*)d_in[7];
    const float* Wqp = (const float*)d_in[8];  const float* bqp = (const float*)d_in[9];
    const float* Wqs = (const float*)d_in[10]; const float* bqs = (const float*)d_in[11];
    const float* Wkc = (const float*)d_in[12]; const float* bkc = (const float*)d_in[13];
    const float* Wkp = (const float*)d_in[14]; const float* bkp = (const float*)d_in[15];
    const float* Wv  = (const float*)d_in[16]; const float* bv  = (const float*)d_in[17];
    const float* Wo  = (const float*)d_in[18]; const float* bo  = (const float*)d_in[19];
    float* out = (float*)d_out;

    const int MK = NK * BATCH;   // 16384
    const int MQ = NQ * BATCH;   // 3600
    const dim3 blk(256);
    const dim3 gK((MK + 63) / 64, CDIM / 64);
    const dim3 gQ((MQ + 63) / 64, CDIM / 64);

    static_assert(ATT_SMEM_FLOATS * 4 == 61184, "smem size");
    cudaFuncSetAttribute(attn_kernel, cudaFuncAttributeMaxDynamicSharedMemorySize,
                         ATT_SMEM_FLOATS * 4);

    // 1. kp -> Kcat[32:64]
    proj_kernel<M_KP><<<gK, blk>>>(keypos, Wkp, bkp, nullptr, nullptr, nullptr,
                                   nullptr, nullptr, MK);
    // 2. k = key@Wkc + kp -> Kcat[0:32]
    proj_kernel<M_KC><<<gK, blk>>>(key, Wkc, bkc, nullptr, nullptr, nullptr,
                                   nullptr, nullptr, MK);
    // 3. v -> Vh
    proj_kernel<M_V><<<gK, blk>>>(value, Wv, bv, nullptr, nullptr, nullptr,
                                  nullptr, nullptr, MK);
    // 4. q = query@Wqc + query_pos@Wqp -> Qcat[0:32] (scaled)
    proj_kernel<M_Q><<<gQ, blk>>>(query, Wqc, bqc, querypos, Wqp, bqp,
                                  nullptr, nullptr, MQ);
    // 5. qse -> Qcat[32:64] (scaled)
    proj_kernel<M_QS><<<gQ, blk>>>(qsine, Wqs, bqs, nullptr, nullptr, nullptr,
                                   nullptr, nullptr, MQ);
    // 6. attention
    attn_kernel<<<dim3((NQ + 63) / 64, 32), blk, ATT_SMEM_FLOATS * 4>>>();
    // 7. out = query + Oattn @ Wo^T + bo
    proj_kernel<M_OUT><<<gQ, blk>>>(nullptr, Wo, bo, nullptr, nullptr, nullptr,
                                    query, out, MQ);
}

// round 3
// speedup vs baseline: 2.1427x; 2.1427x over previous
#include <cuda_runtime.h>
#include <cstdint>
#include <cstddef>

// ---------------------------------------------------------------------------
// Conditional-DETR cross attention — TF32 tensor-core version.
// ---------------------------------------------------------------------------

#define NQ    900
#define NK    4096
#define BATCH 4
#define CDIM  256
#define NH    8
#define DV    32
#define DQK   64
#define QSCALE 0.125f

__device__ float g_Kcat[(size_t)32 * NK * DQK];      // [b*8+h][m][64]
__device__ float g_Vh[(size_t)32 * NK * DV];         // [b*8+h][m][32]
__device__ float g_Qcat[(size_t)32 * NQ * DQK];      // [b*8+h][n][64] (pre-scaled)
__device__ float g_Oattn[(size_t)NQ * BATCH * CDIM]; // [n][b][h*32+v]

#define M_KP  0
#define M_KC  1
#define M_V   2
#define M_Q   3
#define M_QS  4
#define M_OUT 5

__device__ __forceinline__ uint32_t f2tf(float f) {
    uint32_t u; asm("cvt.rna.tf32.f32 %0, %1;" : "=r"(u) : "f"(f)); return u;
}

__device__ __forceinline__ void mma8(float* d, const uint32_t* a, const uint32_t* b) {
    asm volatile(
        "mma.sync.aligned.m16n8k8.row.col.f32.tf32.tf32.f32 "
        "{%0,%1,%2,%3}, {%4,%5,%6,%7}, {%8,%9}, {%0,%1,%2,%3};"
        : "+f"(d[0]), "+f"(d[1]), "+f"(d[2]), "+f"(d[3])
        : "r"(a[0]), "r"(a[1]), "r"(a[2]), "r"(a[3]), "r"(b[0]), "r"(b[1]));
}

// ---------------------------------------------------------------------------
// TF32 mma GEMM: out[row,col] = A[row,:]·W[col,:] + bias[col]; MODE epilogue.
// Block tile 128x64, BK=32, 8 warps (4x2), warp tile 32x32.
// M_Q: K extended to 512 via (A2,W2), bias2 added.
// ---------------------------------------------------------------------------
template<int MODE>
__global__ __launch_bounds__(256)
void proj_mma(const float* __restrict__ A, const float* __restrict__ W,
              const float* __restrict__ bias,
              const float* __restrict__ A2, const float* __restrict__ W2,
              const float* __restrict__ bias2,
              const float* __restrict__ addsrc,
              float* __restrict__ outp, int M)
{
    __shared__ uint32_t As[128][36];
    __shared__ uint32_t Ws[64][36];

    const int tid = threadIdx.x;
    const int w = tid >> 5, lane = tid & 31;
    const int g = lane >> 2, tig = lane & 3;
    const int wm = w >> 1, wn = w & 1;
    const int m0 = blockIdx.x * 128;
    const int c0 = blockIdx.y * 64;

    float acc[2][4][4] = {};

    const int nchunk = (MODE == M_Q) ? 16 : 8;
    for (int kc = 0; kc < nchunk; kc++) {
        const float* Ap = (MODE == M_OUT) ? g_Oattn : A;
        const float* Wp = W;
        int k0 = kc * 32;
        if (MODE == M_Q && kc >= 8) { Ap = A2; Wp = W2; k0 = (kc - 8) * 32; }

        #pragma unroll
        for (int t = 0; t < 4; t++) {
            int i = tid + t * 256;
            int r = i >> 3, k4 = (i & 7) * 4;
            float4 v = make_float4(0.f, 0.f, 0.f, 0.f);
            if (m0 + r < M)
                v = *(const float4*)&Ap[(size_t)(m0 + r) * CDIM + k0 + k4];
            uint4 u = make_uint4(f2tf(v.x), f2tf(v.y), f2tf(v.z), f2tf(v.w));
            *(uint4*)&As[r][k4] = u;
        }
        #pragma unroll
        for (int t = 0; t < 2; t++) {
            int i = tid + t * 256;
            int r = i >> 3, k4 = (i & 7) * 4;
            float4 v = *(const float4*)&Wp[(size_t)(c0 + r) * CDIM + k0 + k4];
            uint4 u = make_uint4(f2tf(v.x), f2tf(v.y), f2tf(v.z), f2tf(v.w));
            *(uint4*)&Ws[r][k4] = u;
        }
        __syncthreads();

        #pragma unroll
        for (int ks = 0; ks < 4; ks++) {
            uint32_t a[2][4], b[4][2];
            #pragma unroll
            for (int mt = 0; mt < 2; mt++) {
                int r = wm * 32 + mt * 16 + g;
                a[mt][0] = As[r][ks * 8 + tig];
                a[mt][1] = As[r + 8][ks * 8 + tig];
                a[mt][2] = As[r][ks * 8 + tig + 4];
                a[mt][3] = As[r + 8][ks * 8 + tig + 4];
            }
            #pragma unroll
            for (int nt = 0; nt < 4; nt++) {
                int c = wn * 32 + nt * 8 + g;
                b[nt][0] = Ws[c][ks * 8 + tig];
                b[nt][1] = Ws[c][ks * 8 + tig + 4];
            }
            #pragma unroll
            for (int mt = 0; mt < 2; mt++)
                #pragma unroll
                for (int nt = 0; nt < 4; nt++)
                    mma8(acc[mt][nt], a[mt], b[nt]);
        }
        __syncthreads();
    }

    #pragma unroll
    for (int mt = 0; mt < 2; mt++)
    #pragma unroll
    for (int nt = 0; nt < 4; nt++)
    #pragma unroll
    for (int cr = 0; cr < 4; cr++) {
        const int row = m0 + wm * 32 + mt * 16 + g + ((cr >= 2) ? 8 : 0);
        if (row >= M) continue;
        const int col = c0 + wn * 32 + nt * 8 + tig * 2 + (cr & 1);
        float val = acc[mt][nt][cr] + bias[col];
        if (MODE == M_Q) val += bias2[col];

        if (MODE == M_KP) {
            const int m = row >> 2, b = row & 3, h = col >> 5, ii = col & 31;
            g_Kcat[((size_t)(b * NH + h) * NK + m) * DQK + 32 + ii] = val;
        } else if (MODE == M_KC) {
            const int m = row >> 2, b = row & 3, h = col >> 5, ii = col & 31;
            const size_t base = ((size_t)(b * NH + h) * NK + m) * DQK;
            g_Kcat[base + ii] = val + g_Kcat[base + 32 + ii];
        } else if (MODE == M_V) {
            const int m = row >> 2, b = row & 3, h = col >> 5, ii = col & 31;
            g_Vh[((size_t)(b * NH + h) * NK + m) * DV + ii] = val;
        } else if (MODE == M_Q) {
            const int n = row >> 2, b = row & 3, h = col >> 5, ii = col & 31;
            g_Qcat[((size_t)(b * NH + h) * NQ + n) * DQK + ii] = val * QSCALE;
        } else if (MODE == M_QS) {
            const int n = row >> 2, b = row & 3, h = col >> 5, ii = col & 31;
            g_Qcat[((size_t)(b * NH + h) * NQ + n) * DQK + 32 + ii] = val * QSCALE;
        } else { // M_OUT
            outp[(size_t)row * CDIM + col] = addsrc[(size_t)row * CDIM + col] + val;
        }
    }
}

// ---------------------------------------------------------------------------
// Flash attention with TF32 mma. Block 256 thr (8 warps, 4x2), 64-query tile.
// ---------------------------------------------------------------------------
#define ATT_SMEM_WORDS (64*68 /*Qs*/ + 64*68 /*Ks*/ + 64*68 /*Ss*/ + 64*40 /*Vs*/ + 3*64)

__global__ __launch_bounds__(256)
void attn_mma()
{
    extern __shared__ uint32_t sm[];
    uint32_t* Qs = sm;                   // [64][68] tf32
    uint32_t* Ks = Qs + 64 * 68;         // [64][68] tf32
    float*    Ss = (float*)(Ks + 64 * 68);   // [64][68] fp32 scores / P
    uint32_t* Vs = (uint32_t*)(Ss) + 64 * 68; // [64][40] tf32
    float* mrow = (float*)(Vs + 64 * 40);
    float* lrow = mrow + 64;
    float* alph = lrow + 64;

    const int tid = threadIdx.x;
    const int w = tid >> 5, lane = tid & 31;
    const int g = lane >> 2, tig = lane & 3;
    const int wm = w >> 1, wn = w & 1;
    const int bh = blockIdx.y;
    const int q0 = blockIdx.x * 64;

    // load Q tile once (tf32)
    #pragma unroll
    for (int t = 0; t < 4; t++) {
        int i = tid + t * 256;
        int r = i >> 4, k4 = (i & 15) * 4;
        float4 v = make_float4(0.f, 0.f, 0.f, 0.f);
        int n = q0 + r;
        if (n < NQ) v = *(const float4*)&g_Qcat[((size_t)bh * NQ + n) * DQK + k4];
        uint4 u = make_uint4(f2tf(v.x), f2tf(v.y), f2tf(v.z), f2tf(v.w));
        *(uint4*)&Qs[r * 68 + k4] = u;
    }
    if (tid < 64) { mrow[tid] = -1e30f; lrow[tid] = 0.f; }

    float oacc[2][4] = {};

    for (int kt = 0; kt < NK / 64; kt++) {
        __syncthreads();
        const int mbase = kt * 64;

        // load K tile (tf32): Ks[key][k]
        #pragma unroll
        for (int t = 0; t < 4; t++) {
            int i = tid + t * 256;
            int r = i >> 4, k4 = (i & 15) * 4;
            float4 v = *(const float4*)&g_Kcat[((size_t)bh * NK + mbase + r) * DQK + k4];
            uint4 u = make_uint4(f2tf(v.x), f2tf(v.y), f2tf(v.z), f2tf(v.w));
            *(uint4*)&Ks[r * 68 + k4] = u;
        }
        // load V tile (tf32): Vs[key][v], stride 40 (conflict-free B frags)
        #pragma unroll
        for (int t = 0; t < 2; t++) {
            int i = tid + t * 256;
            int r = i >> 3, v4 = (i & 7) * 4;
            float4 v = *(const float4*)&g_Vh[((size_t)bh * NK + mbase + r) * DV + v4];
            uint4 u = make_uint4(f2tf(v.x), f2tf(v.y), f2tf(v.z), f2tf(v.w));
            *(uint4*)&Vs[r * 40 + v4] = u;
        }
        __syncthreads();

        // S = Q @ K^T : warp tile 16 rows x 32 cols
        float s[4][4] = {};
        #pragma unroll
        for (int ks = 0; ks < 8; ks++) {
            uint32_t a[4], b[4][2];
            const int r = wm * 16 + g;
            a[0] = Qs[r * 68 + ks * 8 + tig];
            a[1] = Qs[(r + 8) * 68 + ks * 8 + tig];
            a[2] = Qs[r * 68 + ks * 8 + tig + 4];
            a[3] = Qs[(r + 8) * 68 + ks * 8 + tig + 4];
            #pragma unroll
            for (int nt = 0; nt < 4; nt++) {
                int c = wn * 32 + nt * 8 + g;
                b[nt][0] = Ks[c * 68 + ks * 8 + tig];
                b[nt][1] = Ks[c * 68 + ks * 8 + tig + 4];
            }
            #pragma unroll
            for (int nt = 0; nt < 4; nt++) mma8(s[nt], a, b[nt]);
        }
        // write S to smem
        #pragma unroll
        for (int nt = 0; nt < 4; nt++) {
            const int r = wm * 16 + g;
            const int c = wn * 32 + nt * 8 + tig * 2;
            Ss[r * 68 + c] = s[nt][0];
            Ss[r * 68 + c + 1] = s[nt][1];
            Ss[(r + 8) * 68 + c] = s[nt][2];
            Ss[(r + 8) * 68 + c + 1] = s[nt][3];
        }
        __syncthreads();

        // online softmax: row = tid/4, 16-col chunk
        {
            const int r = tid >> 2;
            const int cc = (tid & 3) * 16;
            float mx = -1e30f;
            #pragma unroll
            for (int u = 0; u < 16; u++) mx = fmaxf(mx, Ss[r * 68 + cc + u]);
            mx = fmaxf(mx, __shfl_xor_sync(0xffffffffu, mx, 1));
            mx = fmaxf(mx, __shfl_xor_sync(0xffffffffu, mx, 2));
            const float mo = mrow[r];
            const float mn = fmaxf(mo, mx);
            float sum = 0.f;
            #pragma unroll
            for (int u = 0; u < 16; u++) {
                float p = __expf(Ss[r * 68 + cc + u] - mn);
                Ss[r * 68 + cc + u] = p;
                sum += p;
            }
            sum += __shfl_xor_sync(0xffffffffu, sum, 1);
            sum += __shfl_xor_sync(0xffffffffu, sum, 2);
            if ((tid & 3) == 0) {
                const float al = __expf(mo - mn);
                lrow[r] = lrow[r] * al + sum;
                mrow[r] = mn;
                alph[r] = al;
            }
        }
        __syncthreads();

        // O = O*alpha + P @ V : warp tile 16 rows x 16 cols
        {
            const float al0 = alph[wm * 16 + g];
            const float al1 = alph[wm * 16 + g + 8];
            #pragma unroll
            for (int nt = 0; nt < 2; nt++) {
                oacc[nt][0] *= al0; oacc[nt][1] *= al0;
                oacc[nt][2] *= al1; oacc[nt][3] *= al1;
            }
            #pragma unroll
            for (int ks = 0; ks < 8; ks++) {
                uint32_t a[4], b[2][2];
                const int r = wm * 16 + g;
                a[0] = f2tf(Ss[r * 68 + ks * 8 + tig]);
                a[1] = f2tf(Ss[(r + 8) * 68 + ks * 8 + tig]);
                a[2] = f2tf(Ss[r * 68 + ks * 8 + tig + 4]);
                a[3] = f2tf(Ss[(r + 8) * 68 + ks * 8 + tig + 4]);
                #pragma unroll
                for (int nt = 0; nt < 2; nt++) {
                    int c = wn * 16 + nt * 8 + g;
                    b[nt][0] = Vs[(ks * 8 + tig) * 40 + c];
                    b[nt][1] = Vs[(ks * 8 + tig + 4) * 40 + c];
                }
                #pragma unroll
                for (int nt = 0; nt < 2; nt++) mma8(oacc[nt], a, b[nt]);
            }
        }
    }

    // epilogue: normalize, scatter to [n][b][h*32+v]
    const int b = bh >> 3, h = bh & 7;
    const int r0 = wm * 16 + g;
    const float inv0 = 1.f / lrow[r0];
    const float inv1 = 1.f / lrow[r0 + 8];
    #pragma unroll
    for (int nt = 0; nt < 2; nt++) {
        const int col = h * DV + wn * 16 + nt * 8 + tig * 2;
        const int n0 = q0 + r0;
        if (n0 < NQ) {
            const size_t base = ((size_t)n0 * BATCH + b) * CDIM + col;
            g_Oattn[base]     = oacc[nt][0] * inv0;
            g_Oattn[base + 1] = oacc[nt][1] * inv0;
        }
        const int n1 = n0 + 8;
        if (n1 < NQ) {
            const size_t base = ((size_t)n1 * BATCH + b) * CDIM + col;
            g_Oattn[base]     = oacc[nt][2] * inv1;
            g_Oattn[base + 1] = oacc[nt][3] * inv1;
        }
    }
}

// ---------------------------------------------------------------------------
extern "C" void kernel_launch(void* const* d_in, const int* in_sizes, int n_in,
                              void* d_out, int out_size)
{
    const float* query    = (const float*)d_in[0];
    const float* key      = (const float*)d_in[1];
    const float* value    = (const float*)d_in[2];
    const float* querypos = (const float*)d_in[3];
    const float* keypos   = (const float*)d_in[4];
    const float* qsine    = (const float*)d_in[5];
    const float* Wqc = (const float*)d_in[6];  const float* bqc = (const float*)d_in[7];
    const float* Wqp = (const float*)d_in[8];  const float* bqp = (const float*)d_in[9];
    const float* Wqs = (const float*)d_in[10]; const float* bqs = (const float*)d_in[11];
    const float* Wkc = (const float*)d_in[12]; const float* bkc = (const float*)d_in[13];
    const float* Wkp = (const float*)d_in[14]; const float* bkp = (const float*)d_in[15];
    const float* Wv  = (const float*)d_in[16]; const float* bv  = (const float*)d_in[17];
    const float* Wo  = (const float*)d_in[18]; const float* bo  = (const float*)d_in[19];
    float* out = (float*)d_out;

    const int MK = NK * BATCH;   // 16384
    const int MQ = NQ * BATCH;   // 3600
    const dim3 blk(256);
    const dim3 gK(MK / 128, CDIM / 64);
    const dim3 gQ((MQ + 127) / 128, CDIM / 64);

    cudaFuncSetAttribute(attn_mma, cudaFuncAttributeMaxDynamicSharedMemorySize,
                         ATT_SMEM_WORDS * 4);

    proj_mma<M_KP><<<gK, blk>>>(keypos, Wkp, bkp, nullptr, nullptr, nullptr,
                                nullptr, nullptr, MK);
    proj_mma<M_KC><<<gK, blk>>>(key, Wkc, bkc, nullptr, nullptr, nullptr,
                                nullptr, nullptr, MK);
    proj_mma<M_V><<<gK, blk>>>(value, Wv, bv, nullptr, nullptr, nullptr,
                               nullptr, nullptr, MK);
    proj_mma<M_Q><<<gQ, blk>>>(query, Wqc, bqc, querypos, Wqp, bqp,
                               nullptr, nullptr, MQ);
    proj_mma<M_QS><<<gQ, blk>>>(qsine, Wqs, bqs, nullptr, nullptr, nullptr,
                                nullptr, nullptr, MQ);
    attn_mma<<<dim3((NQ + 63) / 64, 32), blk, ATT_SMEM_WORDS * 4>>>();
    proj_mma<M_OUT><<<gQ, blk>>>(nullptr, Wo, bo, nullptr, nullptr, nullptr,
                                 query, out, MQ);
}

// round 4
// speedup vs baseline: 2.5746x; 1.2016x over previous
#include <cuda_runtime.h>
#include <cstdint>
#include <cstddef>

// ---------------------------------------------------------------------------
// Conditional-DETR cross attention — TF32 mma + cp.async pipelined version.
// ---------------------------------------------------------------------------

#define NQ    900
#define NK    4096
#define BATCH 4
#define CDIM  256
#define NH    8
#define DV    32
#define DQK   64
#define QSCALE 0.125f

// scratch: K/Q/V stored as TF32 bit patterns (pre-converted in proj epilogues)
__device__ uint32_t g_Kcat[(size_t)32 * NK * DQK];   // [b*8+h][m][64]
__device__ uint32_t g_Vh[(size_t)32 * NK * DV];      // [b*8+h][m][32]
__device__ uint32_t g_Qcat[(size_t)32 * NQ * DQK];   // [b*8+h][n][64] (pre-scaled)
__device__ float    g_Oattn[(size_t)NQ * BATCH * CDIM]; // [n][b][h*32+v]

#define M_KPC  0
#define M_V    1
#define M_QALL 2
#define M_OUT  3

__device__ __forceinline__ uint32_t f2tf(float f) {
    uint32_t u; asm("cvt.rna.tf32.f32 %0, %1;" : "=r"(u) : "f"(f)); return u;
}

__device__ __forceinline__ void mma8(float* d, const uint32_t* a, const uint32_t* b) {
    asm volatile(
        "mma.sync.aligned.m16n8k8.row.col.f32.tf32.tf32.f32 "
        "{%0,%1,%2,%3}, {%4,%5,%6,%7}, {%8,%9}, {%0,%1,%2,%3};"
        : "+f"(d[0]), "+f"(d[1]), "+f"(d[2]), "+f"(d[3])
        : "r"(a[0]), "r"(a[1]), "r"(a[2]), "r"(a[3]), "r"(b[0]), "r"(b[1]));
}

__device__ __forceinline__ void cpa16(uint32_t dst, const void* src, int sz) {
    asm volatile("cp.async.cg.shared.global [%0], [%1], 16, %2;"
                 :: "r"(dst), "l"(src), "r"(sz));
}
#define CP_COMMIT asm volatile("cp.async.commit_group;" ::: "memory")
#define CP_WAIT0  asm volatile("cp.async.wait_group 0;" ::: "memory")
#define CP_WAIT1  asm volatile("cp.async.wait_group 1;" ::: "memory")

// ---------------------------------------------------------------------------
// Pipelined TF32 GEMM, block tile 128x64, BK=32, 8 warps (4x2), warp 32x32.
// Multi-phase accumulation:
//   M_KPC : kc[0,8)->acc0 (key@Wkc), kc[8,16)->acc1 (keypos@Wkp)
//   M_QALL: kc[0,8)->acc0 (query@Wqc), [8,16)->acc0 (qpos@Wqp), [16,24)->acc1 (qsine@Wqs)
//   M_V / M_OUT: 8 chunks -> acc0
// ---------------------------------------------------------------------------
#define PROJ_SMEM ((2*128*36 + 2*64*36) * 4)

template<int MODE>
__device__ __forceinline__ void pickAW(int kc,
    const float* A0, const float* A1, const float* A2,
    const float* W0, const float* W1, const float* W2,
    const float*& Ap, const float*& Wp, int& k0)
{
    if (MODE == M_KPC) {
        if (kc < 8) { Ap = A0; Wp = W0; k0 = kc * 32; }
        else        { Ap = A1; Wp = W1; k0 = (kc - 8) * 32; }
    } else if (MODE == M_QALL) {
        if (kc < 8)       { Ap = A0; Wp = W0; k0 = kc * 32; }
        else if (kc < 16) { Ap = A1; Wp = W1; k0 = (kc - 8) * 32; }
        else              { Ap = A2; Wp = W2; k0 = (kc - 16) * 32; }
    } else if (MODE == M_OUT) {
        Ap = g_Oattn; Wp = W0; k0 = kc * 32;
    } else {
        Ap = A0; Wp = W0; k0 = kc * 32;
    }
}

template<int MODE>
__global__ __launch_bounds__(256)
void proj_mma(const float* __restrict__ A0, const float* __restrict__ A1,
              const float* __restrict__ A2,
              const float* __restrict__ W0, const float* __restrict__ W1,
              const float* __restrict__ W2,
              const float* __restrict__ b0a, const float* __restrict__ b0b,
              const float* __restrict__ b1,
              const float* __restrict__ addsrc, float* __restrict__ outp, int M)
{
    extern __shared__ float psm[];
    float* As = psm;                 // [2][128][36]
    float* Ws = psm + 2 * 128 * 36;  // [2][64][36]
    const uint32_t asB = (uint32_t)__cvta_generic_to_shared(As);
    const uint32_t wsB = (uint32_t)__cvta_generic_to_shared(Ws);

    const int tid = threadIdx.x;
    const int w = tid >> 5, lane = tid & 31;
    const int g = lane >> 2, tig = lane & 3;
    const int wm = w >> 1, wn = w & 1;
    const int m0 = blockIdx.x * 128;
    const int c0 = blockIdx.y * 64;

    float acc0[2][4][4] = {};
    float acc1[2][4][4] = {};
    const int nchunk = (MODE == M_KPC) ? 16 : (MODE == M_QALL) ? 24 : 8;

    auto load_chunk = [&](int kc, int buf) {
        const float *Ap, *Wp; int k0;
        pickAW<MODE>(kc, A0, A1, A2, W0, W1, W2, Ap, Wp, k0);
        #pragma unroll
        for (int t = 0; t < 4; t++) {
            int i = tid + t * 256;
            int r = i >> 3, s = (i & 7) * 4;
            int row = m0 + r;
            uint32_t dst = asB + (((buf * 128 + r) * 36 + s) << 2);
            cpa16(dst, Ap + (size_t)row * CDIM + k0 + s, row < M ? 16 : 0);
        }
        #pragma unroll
        for (int t = 0; t < 2; t++) {
            int i = tid + t * 256;
            int r = i >> 3, s = (i & 7) * 4;
            uint32_t dst = wsB + (((buf * 64 + r) * 36 + s) << 2);
            cpa16(dst, Wp + (size_t)(c0 + r) * CDIM + k0 + s, 16);
        }
    };

    auto compute = [&](int buf, float (&acc)[2][4][4]) {
        const float* Ab = As + buf * 128 * 36;
        const float* Wb = Ws + buf * 64 * 36;
        #pragma unroll
        for (int ks = 0; ks < 4; ks++) {
            uint32_t a[2][4], b[4][2];
            #pragma unroll
            for (int mt = 0; mt < 2; mt++) {
                int r = wm * 32 + mt * 16 + g;
                a[mt][0] = f2tf(Ab[r * 36 + ks * 8 + tig]);
                a[mt][1] = f2tf(Ab[(r + 8) * 36 + ks * 8 + tig]);
                a[mt][2] = f2tf(Ab[r * 36 + ks * 8 + tig + 4]);
                a[mt][3] = f2tf(Ab[(r + 8) * 36 + ks * 8 + tig + 4]);
            }
            #pragma unroll
            for (int nt = 0; nt < 4; nt++) {
                int c = wn * 32 + nt * 8 + g;
                b[nt][0] = f2tf(Wb[c * 36 + ks * 8 + tig]);
                b[nt][1] = f2tf(Wb[c * 36 + ks * 8 + tig + 4]);
            }
            #pragma unroll
            for (int mt = 0; mt < 2; mt++)
                #pragma unroll
                for (int nt = 0; nt < 4; nt++)
                    mma8(acc[mt][nt], a[mt], b[nt]);
        }
    };

    load_chunk(0, 0);
    CP_COMMIT;
    for (int kc = 0; kc < nchunk; kc++) {
        if (kc + 1 < nchunk) { load_chunk(kc + 1, (kc + 1) & 1); CP_COMMIT; CP_WAIT1; }
        else                 { CP_WAIT0; }
        __syncthreads();
        const bool sec = (MODE == M_KPC && kc >= 8) || (MODE == M_QALL && kc >= 16);
        if (sec) compute(kc & 1, acc1);
        else     compute(kc & 1, acc0);
        __syncthreads();
    }

    #pragma unroll
    for (int mt = 0; mt < 2; mt++)
    #pragma unroll
    for (int nt = 0; nt < 4; nt++)
    #pragma unroll
    for (int cr = 0; cr < 4; cr++) {
        const int row = m0 + wm * 32 + mt * 16 + g + ((cr >= 2) ? 8 : 0);
        if (row >= M) continue;
        const int col = c0 + wn * 32 + nt * 8 + tig * 2 + (cr & 1);

        if (MODE == M_KPC) {
            const int m = row >> 2, b = row & 3, h = col >> 5, ii = col & 31;
            const float vkp = acc1[mt][nt][cr] + b1[col];
            const float vk  = acc0[mt][nt][cr] + b0a[col] + vkp;
            const size_t base = ((size_t)(b * NH + h) * NK + m) * DQK;
            g_Kcat[base + ii]      = f2tf(vk);
            g_Kcat[base + 32 + ii] = f2tf(vkp);
        } else if (MODE == M_V) {
            const int m = row >> 2, b = row & 3, h = col >> 5, ii = col & 31;
            g_Vh[((size_t)(b * NH + h) * NK + m) * DV + ii] =
                f2tf(acc0[mt][nt][cr] + b0a[col]);
        } else if (MODE == M_QALL) {
            const int n = row >> 2, b = row & 3, h = col >> 5, ii = col & 31;
            const size_t base = ((size_t)(b * NH + h) * NQ + n) * DQK;
            g_Qcat[base + ii] =
                f2tf((acc0[mt][nt][cr] + b0a[col] + b0b[col]) * QSCALE);
            g_Qcat[base + 32 + ii] =
                f2tf((acc1[mt][nt][cr] + b1[col]) * QSCALE);
        } else { // M_OUT
            outp[(size_t)row * CDIM + col] =
                addsrc[(size_t)row * CDIM + col] + acc0[mt][nt][cr] + b0a[col];
        }
    }
}

// ---------------------------------------------------------------------------
// Flash attention, TF32 mma, cp.async double-buffered K/V. 8 warps (4x2).
// All K/V/Q already in TF32 bits -> mainloop has zero cvt except P.
// ---------------------------------------------------------------------------
#define ATT_SMEM_WORDS (64*68 /*Qs*/ + 2*64*68 /*Ks*/ + 64*68 /*Ss*/ + 2*64*40 /*Vs*/ + 3*64)

__global__ __launch_bounds__(256)
void attn_mma()
{
    extern __shared__ uint32_t sm[];
    uint32_t* Qs = sm;                       // [64][68]
    uint32_t* Ks = Qs + 64 * 68;             // [2][64][68]
    float*    Ss = (float*)(Ks + 2 * 64 * 68); // [64][68]
    uint32_t* Vs = (uint32_t*)Ss + 64 * 68;  // [2][64][40]
    float* mrow = (float*)(Vs + 2 * 64 * 40);
    float* lrow = mrow + 64;
    float* alph = lrow + 64;
    const uint32_t ksB = (uint32_t)__cvta_generic_to_shared(Ks);
    const uint32_t vsB = (uint32_t)__cvta_generic_to_shared(Vs);

    const int tid = threadIdx.x;
    const int w = tid >> 5, lane = tid & 31;
    const int g = lane >> 2, tig = lane & 3;
    const int wm = w >> 1, wn = w & 1;
    const int bh = blockIdx.y;
    const int q0 = blockIdx.x * 64;

    // Q tile (already TF32 bits)
    #pragma unroll
    for (int t = 0; t < 4; t++) {
        int i = tid + t * 256;
        int r = i >> 4, k4 = (i & 15) * 4;
        uint4 u = make_uint4(0u, 0u, 0u, 0u);
        int n = q0 + r;
        if (n < NQ) u = *(const uint4*)&g_Qcat[((size_t)bh * NQ + n) * DQK + k4];
        *(uint4*)&Qs[r * 68 + k4] = u;
    }
    if (tid < 64) { mrow[tid] = -1e30f; lrow[tid] = 0.f; }

    auto issueKV = [&](int kt, int buf) {
        const int mbase = kt * 64;
        #pragma unroll
        for (int t = 0; t < 4; t++) {
            int i = tid + t * 256;
            int r = i >> 4, s = (i & 15) * 4;
            uint32_t dst = ksB + (((buf * 64 + r) * 68 + s) << 2);
            cpa16(dst, &g_Kcat[((size_t)bh * NK + mbase + r) * DQK + s], 16);
        }
        #pragma unroll
        for (int t = 0; t < 2; t++) {
            int i = tid + t * 256;
            int r = i >> 3, s = (i & 7) * 4;
            uint32_t dst = vsB + (((buf * 64 + r) * 40 + s) << 2);
            cpa16(dst, &g_Vh[((size_t)bh * NK + mbase + r) * DV + s], 16);
        }
    };

    float oacc[2][4] = {};

    issueKV(0, 0);
    CP_COMMIT;

    for (int kt = 0; kt < NK / 64; kt++) {
        const int buf = kt & 1;
        if (kt + 1 < NK / 64) { issueKV(kt + 1, buf ^ 1); CP_COMMIT; CP_WAIT1; }
        else                  { CP_WAIT0; }
        __syncthreads();

        const uint32_t* Kb = Ks + buf * 64 * 68;
        const uint32_t* Vb = Vs + buf * 64 * 40;

        // S = Q @ K^T : warp tile 16 x 32
        float s[4][4] = {};
        #pragma unroll
        for (int ks = 0; ks < 8; ks++) {
            uint32_t a[4], b[4][2];
            const int r = wm * 16 + g;
            a[0] = Qs[r * 68 + ks * 8 + tig];
            a[1] = Qs[(r + 8) * 68 + ks * 8 + tig];
            a[2] = Qs[r * 68 + ks * 8 + tig + 4];
            a[3] = Qs[(r + 8) * 68 + ks * 8 + tig + 4];
            #pragma unroll
            for (int nt = 0; nt < 4; nt++) {
                int c = wn * 32 + nt * 8 + g;
                b[nt][0] = Kb[c * 68 + ks * 8 + tig];
                b[nt][1] = Kb[c * 68 + ks * 8 + tig + 4];
            }
            #pragma unroll
            for (int nt = 0; nt < 4; nt++) mma8(s[nt], a, b[nt]);
        }
        #pragma unroll
        for (int nt = 0; nt < 4; nt++) {
            const int r = wm * 16 + g;
            const int c = wn * 32 + nt * 8 + tig * 2;
            Ss[r * 68 + c] = s[nt][0];
            Ss[r * 68 + c + 1] = s[nt][1];
            Ss[(r + 8) * 68 + c] = s[nt][2];
            Ss[(r + 8) * 68 + c + 1] = s[nt][3];
        }
        __syncthreads();

        // online softmax
        {
            const int r = tid >> 2;
            const int cc = (tid & 3) * 16;
            float mx = -1e30f;
            #pragma unroll
            for (int u = 0; u < 16; u++) mx = fmaxf(mx, Ss[r * 68 + cc + u]);
            mx = fmaxf(mx, __shfl_xor_sync(0xffffffffu, mx, 1));
            mx = fmaxf(mx, __shfl_xor_sync(0xffffffffu, mx, 2));
            const float mo = mrow[r];
            const float mn = fmaxf(mo, mx);
            float sum = 0.f;
            #pragma unroll
            for (int u = 0; u < 16; u++) {
                float p = __expf(Ss[r * 68 + cc + u] - mn);
                Ss[r * 68 + cc + u] = p;
                sum += p;
            }
            sum += __shfl_xor_sync(0xffffffffu, sum, 1);
            sum += __shfl_xor_sync(0xffffffffu, sum, 2);
            if ((tid & 3) == 0) {
                const float al = __expf(mo - mn);
                lrow[r] = lrow[r] * al + sum;
                mrow[r] = mn;
                alph[r] = al;
            }
        }
        __syncthreads();

        // O = O*alpha + P @ V : warp tile 16 x 16
        {
            const float al0 = alph[wm * 16 + g];
            const float al1 = alph[wm * 16 + g + 8];
            #pragma unroll
            for (int nt = 0; nt < 2; nt++) {
                oacc[nt][0] *= al0; oacc[nt][1] *= al0;
                oacc[nt][2] *= al1; oacc[nt][3] *= al1;
            }
            #pragma unroll
            for (int ks = 0; ks < 8; ks++) {
                uint32_t a[4], b[2][2];
                const int r = wm * 16 + g;
                a[0] = f2tf(Ss[r * 68 + ks * 8 + tig]);
                a[1] = f2tf(Ss[(r + 8) * 68 + ks * 8 + tig]);
                a[2] = f2tf(Ss[r * 68 + ks * 8 + tig + 4]);
                a[3] = f2tf(Ss[(r + 8) * 68 + ks * 8 + tig + 4]);
                #pragma unroll
                for (int nt = 0; nt < 2; nt++) {
                    int c = wn * 16 + nt * 8 + g;
                    b[nt][0] = Vb[(ks * 8 + tig) * 40 + c];
                    b[nt][1] = Vb[(ks * 8 + tig + 4) * 40 + c];
                }
                #pragma unroll
                for (int nt = 0; nt < 2; nt++) mma8(oacc[nt], a, b[nt]);
            }
        }
        __syncthreads();   // PV done before next issue overwrites this buffer
    }

    const int b = bh >> 3, h = bh & 7;
    const int r0 = wm * 16 + g;
    const float inv0 = 1.f / lrow[r0];
    const float inv1 = 1.f / lrow[r0 + 8];
    #pragma unroll
    for (int nt = 0; nt < 2; nt++) {
        const int col = h * DV + wn * 16 + nt * 8 + tig * 2;
        const int n0 = q0 + r0;
        if (n0 < NQ) {
            const size_t base = ((size_t)n0 * BATCH + b) * CDIM + col;
            g_Oattn[base]     = oacc[nt][0] * inv0;
            g_Oattn[base + 1] = oacc[nt][1] * inv0;
        }
        const int n1 = n0 + 8;
        if (n1 < NQ) {
            const size_t base = ((size_t)n1 * BATCH + b) * CDIM + col;
            g_Oattn[base]     = oacc[nt][2] * inv1;
            g_Oattn[base + 1] = oacc[nt][3] * inv1;
        }
    }
}

// ---------------------------------------------------------------------------
extern "C" void kernel_launch(void* const* d_in, const int* in_sizes, int n_in,
                              void* d_out, int out_size)
{
    const float* query    = (const float*)d_in[0];
    const float* key      = (const float*)d_in[1];
    const float* value    = (const float*)d_in[2];
    const float* querypos = (const float*)d_in[3];
    const float* keypos   = (const float*)d_in[4];
    const float* qsine    = (const float*)d_in[5];
    const float* Wqc = (const float*)d_in[6];  const float* bqc = (const float*)d_in[7];
    const float* Wqp = (const float*)d_in[8];  const float* bqp = (const float*)d_in[9];
    const float* Wqs = (const float*)d_in[10]; const float* bqs = (const float*)d_in[11];
    const float* Wkc = (const float*)d_in[12]; const float* bkc = (const float*)d_in[13];
    const float* Wkp = (const float*)d_in[14]; const float* bkp = (const float*)d_in[15];
    const float* Wv  = (const float*)d_in[16]; const float* bv  = (const float*)d_in[17];
    const float* Wo  = (const float*)d_in[18]; const float* bo  = (const float*)d_in[19];
    float* out = (float*)d_out;

    const int MK = NK * BATCH;   // 16384
    const int MQ = NQ * BATCH;   // 3600
    const dim3 blk(256);
    const dim3 gK(MK / 128, CDIM / 64);
    const dim3 gQ((MQ + 127) / 128, CDIM / 64);

    static bool attr_done = false;
    if (!attr_done) {
        cudaFuncSetAttribute(proj_mma<M_KPC>, cudaFuncAttributeMaxDynamicSharedMemorySize, PROJ_SMEM);
        cudaFuncSetAttribute(proj_mma<M_V>,   cudaFuncAttributeMaxDynamicSharedMemorySize, PROJ_SMEM);
        cudaFuncSetAttribute(proj_mma<M_QALL>,cudaFuncAttributeMaxDynamicSharedMemorySize, PROJ_SMEM);
        cudaFuncSetAttribute(proj_mma<M_OUT>, cudaFuncAttributeMaxDynamicSharedMemorySize, PROJ_SMEM);
        cudaFuncSetAttribute(attn_mma, cudaFuncAttributeMaxDynamicSharedMemorySize, ATT_SMEM_WORDS * 4);
        attr_done = true;
    }

    // 1. Kcat[0:32]=key@Wkc+bkc+kp, Kcat[32:64]=kp  (kp=keypos@Wkp+bkp)
    proj_mma<M_KPC><<<gK, blk, PROJ_SMEM>>>(key, keypos, nullptr,
                                            Wkc, Wkp, nullptr,
                                            bkc, nullptr, bkp,
                                            nullptr, nullptr, MK);
    // 2. Vh = value@Wv+bv
    proj_mma<M_V><<<gK, blk, PROJ_SMEM>>>(value, nullptr, nullptr,
                                          Wv, nullptr, nullptr,
                                          bv, nullptr, nullptr,
                                          nullptr, nullptr, MK);
    // 3. Qcat[0:32]=(query@Wqc+qpos@Wqp+bqc+bqp)*s, Qcat[32:64]=(qsine@Wqs+bqs)*s
    proj_mma<M_QALL><<<gQ, blk, PROJ_SMEM>>>(query, querypos, qsine,
                                             Wqc, Wqp, Wqs,
                                             bqc, bqp, bqs,
                                             nullptr, nullptr, MQ);
    // 4. attention
    attn_mma<<<dim3((NQ + 63) / 64, 32), blk, ATT_SMEM_WORDS * 4>>>();
    // 5. out = query + Oattn@Wo + bo
    proj_mma<M_OUT><<<gQ, blk, PROJ_SMEM>>>(nullptr, nullptr, nullptr,
                                            Wo, nullptr, nullptr,
                                            bo, nullptr, nullptr,
                                            query, out, MQ);
}

// round 5
// speedup vs baseline: 2.9867x; 1.1601x over previous
#include <cuda_runtime.h>
#include <cstdint>
#include <cstddef>

// ---------------------------------------------------------------------------
// Conditional-DETR cross attention — TF32 mma, register-resident split-K flash.
// ---------------------------------------------------------------------------

#define NQ    900
#define NK    4096
#define BATCH 4
#define CDIM  256
#define NH    8
#define DV    32
#define DQK   64
#define QSCALE 0.125f

// scratch (TF32 bit patterns, pre-converted in proj epilogues)
// K: [bh][key][64]  with head-dim permuted within 16-groups (fragment-friendly)
// V: [bh*32+vcol][key] transposed, key permuted within 16-groups
// Q: [bh][n][64]    plain logical order (pre-scaled)
__device__ uint32_t g_Kcat[(size_t)32 * NK * DQK];
__device__ uint32_t g_Vh[(size_t)32 * DV * NK];
__device__ uint32_t g_Qcat[(size_t)32 * NQ * DQK];
__device__ float    g_Oattn[(size_t)NQ * BATCH * CDIM]; // [n][b][h*32+v]

#define M_KPC  0
#define M_V    1
#define M_QALL 2
#define M_OUT  3

__device__ __forceinline__ uint32_t f2tf(float f) {
    uint32_t u; asm("cvt.rna.tf32.f32 %0, %1;" : "=r"(u) : "f"(f)); return u;
}

__device__ __forceinline__ void mma8(float* d, const uint32_t* a, const uint32_t* b) {
    asm volatile(
        "mma.sync.aligned.m16n8k8.row.col.f32.tf32.tf32.f32 "
        "{%0,%1,%2,%3}, {%4,%5,%6,%7}, {%8,%9}, {%0,%1,%2,%3};"
        : "+f"(d[0]), "+f"(d[1]), "+f"(d[2]), "+f"(d[3])
        : "r"(a[0]), "r"(a[1]), "r"(a[2]), "r"(a[3]), "r"(b[0]), "r"(b[1]));
}

__device__ __forceinline__ void cpa16(uint32_t dst, const void* src, int sz) {
    asm volatile("cp.async.cg.shared.global [%0], [%1], 16, %2;"
                 :: "r"(dst), "l"(src), "r"(sz));
}
#define CP_COMMIT asm volatile("cp.async.commit_group;" ::: "memory")
#define CP_WAIT0  asm volatile("cp.async.wait_group 0;" ::: "memory")
#define CP_WAIT1  asm volatile("cp.async.wait_group 1;" ::: "memory")

// store index k at perm16(k): within each 16-group, (4a+b) -> (4b+a).
// Then a thread's uint4 at col 4*tig of a group holds logical {tig,tig+4,tig+8,tig+12}.
__device__ __host__ __forceinline__ int perm16(int k) {
    return (k & ~15) | ((k & 3) << 2) | ((k >> 2) & 3);
}

__device__ __forceinline__ uint32_t uelem(const uint4& v, int e) {
    return e == 0 ? v.x : e == 1 ? v.y : e == 2 ? v.z : v.w;
}

// ---------------------------------------------------------------------------
// Pipelined TF32 GEMM (same as round 4; epilogues write permuted layouts).
// ---------------------------------------------------------------------------
#define PROJ_SMEM ((2*128*36 + 2*64*36) * 4)

template<int MODE>
__device__ __forceinline__ void pickAW(int kc,
    const float* A0, const float* A1, const float* A2,
    const float* W0, const float* W1, const float* W2,
    const float*& Ap, const float*& Wp, int& k0)
{
    if (MODE == M_KPC) {
        if (kc < 8) { Ap = A0; Wp = W0; k0 = kc * 32; }
        else        { Ap = A1; Wp = W1; k0 = (kc - 8) * 32; }
    } else if (MODE == M_QALL) {
        if (kc < 8)       { Ap = A0; Wp = W0; k0 = kc * 32; }
        else if (kc < 16) { Ap = A1; Wp = W1; k0 = (kc - 8) * 32; }
        else              { Ap = A2; Wp = W2; k0 = (kc - 16) * 32; }
    } else if (MODE == M_OUT) {
        Ap = g_Oattn; Wp = W0; k0 = kc * 32;
    } else {
        Ap = A0; Wp = W0; k0 = kc * 32;
    }
}

template<int MODE>
__global__ __launch_bounds__(256)
void proj_mma(const float* __restrict__ A0, const float* __restrict__ A1,
              const float* __restrict__ A2,
              const float* __restrict__ W0, const float* __restrict__ W1,
              const float* __restrict__ W2,
              const float* __restrict__ b0a, const float* __restrict__ b0b,
              const float* __restrict__ b1,
              const float* __restrict__ addsrc, float* __restrict__ outp, int M)
{
    extern __shared__ float psm[];
    float* As = psm;                 // [2][128][36]
    float* Ws = psm + 2 * 128 * 36;  // [2][64][36]
    const uint32_t asB = (uint32_t)__cvta_generic_to_shared(As);
    const uint32_t wsB = (uint32_t)__cvta_generic_to_shared(Ws);

    const int tid = threadIdx.x;
    const int w = tid >> 5, lane = tid & 31;
    const int g = lane >> 2, tig = lane & 3;
    const int wm = w >> 1, wn = w & 1;
    const int m0 = blockIdx.x * 128;
    const int c0 = blockIdx.y * 64;

    float acc0[2][4][4] = {};
    float acc1[2][4][4] = {};
    const int nchunk = (MODE == M_KPC) ? 16 : (MODE == M_QALL) ? 24 : 8;

    auto load_chunk = [&](int kc, int buf) {
        const float *Ap, *Wp; int k0;
        pickAW<MODE>(kc, A0, A1, A2, W0, W1, W2, Ap, Wp, k0);
        #pragma unroll
        for (int t = 0; t < 4; t++) {
            int i = tid + t * 256;
            int r = i >> 3, s = (i & 7) * 4;
            int row = m0 + r;
            uint32_t dst = asB + (((buf * 128 + r) * 36 + s) << 2);
            cpa16(dst, Ap + (size_t)row * CDIM + k0 + s, row < M ? 16 : 0);
        }
        #pragma unroll
        for (int t = 0; t < 2; t++) {
            int i = tid + t * 256;
            int r = i >> 3, s = (i & 7) * 4;
            uint32_t dst = wsB + (((buf * 64 + r) * 36 + s) << 2);
            cpa16(dst, Wp + (size_t)(c0 + r) * CDIM + k0 + s, 16);
        }
    };

    auto compute = [&](int buf, float (&acc)[2][4][4]) {
        const float* Ab = As + buf * 128 * 36;
        const float* Wb = Ws + buf * 64 * 36;
        #pragma unroll
        for (int ks = 0; ks < 4; ks++) {
            uint32_t a[2][4], b[4][2];
            #pragma unroll
            for (int mt = 0; mt < 2; mt++) {
                int r = wm * 32 + mt * 16 + g;
                a[mt][0] = f2tf(Ab[r * 36 + ks * 8 + tig]);
                a[mt][1] = f2tf(Ab[(r + 8) * 36 + ks * 8 + tig]);
                a[mt][2] = f2tf(Ab[r * 36 + ks * 8 + tig + 4]);
                a[mt][3] = f2tf(Ab[(r + 8) * 36 + ks * 8 + tig + 4]);
            }
            #pragma unroll
            for (int nt = 0; nt < 4; nt++) {
                int c = wn * 32 + nt * 8 + g;
                b[nt][0] = f2tf(Wb[c * 36 + ks * 8 + tig]);
                b[nt][1] = f2tf(Wb[c * 36 + ks * 8 + tig + 4]);
            }
            #pragma unroll
            for (int mt = 0; mt < 2; mt++)
                #pragma unroll
                for (int nt = 0; nt < 4; nt++)
                    mma8(acc[mt][nt], a[mt], b[nt]);
        }
    };

    load_chunk(0, 0);
    CP_COMMIT;
    for (int kc = 0; kc < nchunk; kc++) {
        if (kc + 1 < nchunk) { load_chunk(kc + 1, (kc + 1) & 1); CP_COMMIT; CP_WAIT1; }
        else                 { CP_WAIT0; }
        __syncthreads();
        const bool sec = (MODE == M_KPC && kc >= 8) || (MODE == M_QALL && kc >= 16);
        if (sec) compute(kc & 1, acc1);
        else     compute(kc & 1, acc0);
        __syncthreads();
    }

    #pragma unroll
    for (int mt = 0; mt < 2; mt++)
    #pragma unroll
    for (int nt = 0; nt < 4; nt++)
    #pragma unroll
    for (int cr = 0; cr < 4; cr++) {
        const int row = m0 + wm * 32 + mt * 16 + g + ((cr >= 2) ? 8 : 0);
        if (row >= M) continue;
        const int col = c0 + wn * 32 + nt * 8 + tig * 2 + (cr & 1);

        if (MODE == M_KPC) {
            const int m = row >> 2, b = row & 3, h = col >> 5, ii = col & 31;
            const float vkp = acc1[mt][nt][cr] + b1[col];
            const float vk  = acc0[mt][nt][cr] + b0a[col] + vkp;
            const size_t base = ((size_t)(b * NH + h) * NK + m) * DQK;
            const int ip = perm16(ii);
            g_Kcat[base + ip]      = f2tf(vk);
            g_Kcat[base + 32 + ip] = f2tf(vkp);
        } else if (MODE == M_V) {
            const int m = row >> 2, b = row & 3, h = col >> 5, ii = col & 31;
            // transposed + key-permuted V
            g_Vh[((size_t)(b * NH + h) * DV + ii) * NK + perm16(m)] =
                f2tf(acc0[mt][nt][cr] + b0a[col]);
        } else if (MODE == M_QALL) {
            const int n = row >> 2, b = row & 3, h = col >> 5, ii = col & 31;
            const size_t base = ((size_t)(b * NH + h) * NQ + n) * DQK;
            g_Qcat[base + ii] =
                f2tf((acc0[mt][nt][cr] + b0a[col] + b0b[col]) * QSCALE);
            g_Qcat[base + 32 + ii] =
                f2tf((acc1[mt][nt][cr] + b1[col]) * QSCALE);
        } else { // M_OUT
            outp[(size_t)row * CDIM + col] =
                addsrc[(size_t)row * CDIM + col] + acc0[mt][nt][cr] + b0a[col];
        }
    }
}

// ---------------------------------------------------------------------------
// Flash attention: register-resident split-K. 8 warps (wm 0..3 rows, wn 0..1 keys).
// Each (wm,wn) warp runs an independent flash pass over its 32-key strips;
// the wn pair merges (m,l,O) once at the end.
// ---------------------------------------------------------------------------
#define ATT_SMEM_BYTES ((64*72 + 2*64*72 + 2*32*72) * 4)   // Q + K(2) + V(2) = 72KB

__global__ __launch_bounds__(256, 2)
void attn_mma()
{
    extern __shared__ uint32_t sm[];
    uint32_t* Qs = sm;                     // [64][72]
    uint32_t* Ks = Qs + 64 * 72;           // [2][64][72]
    uint32_t* Vs = Ks + 2 * 64 * 72;       // [2][32][72]
    float* Os = (float*)Ks;                // epilogue reuse [64][36]
    float* Ml = (float*)Vs;                // epilogue reuse [64][4]
    const uint32_t qsB = (uint32_t)__cvta_generic_to_shared(Qs);
    const uint32_t ksB = (uint32_t)__cvta_generic_to_shared(Ks);
    const uint32_t vsB = (uint32_t)__cvta_generic_to_shared(Vs);

    const int tid = threadIdx.x;
    const int w = tid >> 5, lane = tid & 31;
    const int g = lane >> 2, tig = lane & 3;
    const int wm = w >> 1, wn = w & 1;
    const int bh = blockIdx.y;
    const int q0 = blockIdx.x * 64;

    auto issueQ = [&]() {
        #pragma unroll
        for (int t = 0; t < 4; t++) {
            int i = tid + t * 256;
            int r = i >> 4, s = (i & 15) * 4;
            int n = q0 + r;
            uint32_t dst = qsB + ((r * 72 + s) << 2);
            cpa16(dst, &g_Qcat[((size_t)bh * NQ + (n < NQ ? n : 0)) * DQK + s],
                  n < NQ ? 16 : 0);
        }
    };
    auto issueKV = [&](int kt, int buf) {
        const int mbase = kt * 64;
        #pragma unroll
        for (int t = 0; t < 4; t++) {
            int i = tid + t * 256;
            int r = i >> 4, s = (i & 15) * 4;
            uint32_t dst = ksB + (((buf * 64 + r) * 72 + s) << 2);
            cpa16(dst, &g_Kcat[((size_t)bh * NK + mbase + r) * DQK + s], 16);
        }
        #pragma unroll
        for (int t = 0; t < 2; t++) {
            int i = tid + t * 256;
            int r = i >> 4, s = (i & 15) * 4;
            uint32_t dst = vsB + (((buf * 32 + r) * 72 + s) << 2);
            cpa16(dst, &g_Vh[((size_t)bh * DV + r) * NK + mbase + s], 16);
        }
    };

    issueQ();
    issueKV(0, 0);
    CP_COMMIT;

    uint32_t qa[8][4];              // Q fragments, constant across tiles
    float oacc[4][4] = {};          // rows {g,g+8} x vcols {nt*8+tig*2,+1}
    float m0 = -1e30f, m1 = -1e30f, l0 = 0.f, l1 = 0.f;

    const int NT = NK / 64;
    for (int kt = 0; kt < NT; kt++) {
        const int buf = kt & 1;
        if (kt + 1 < NT) { issueKV(kt + 1, buf ^ 1); CP_COMMIT; CP_WAIT1; }
        else             { CP_WAIT0; }
        __syncthreads();

        if (kt == 0) {   // hoist Q fragments into registers
            const int r = wm * 16 + g;
            #pragma unroll
            for (int ks = 0; ks < 8; ks++) {
                qa[ks][0] = Qs[r * 72 + ks * 8 + tig];
                qa[ks][1] = Qs[(r + 8) * 72 + ks * 8 + tig];
                qa[ks][2] = Qs[r * 72 + ks * 8 + tig + 4];
                qa[ks][3] = Qs[(r + 8) * 72 + ks * 8 + tig + 4];
            }
        }

        const uint32_t* Kb = Ks + buf * 64 * 72;
        const uint32_t* Vb = Vs + buf * 32 * 72;

        // ---- S = Q @ K^T over this warp's 32-key strip (regs only) ----
        float s[4][4];
        #pragma unroll
        for (int nt = 0; nt < 4; nt++) {
            const int krow = wn * 32 + nt * 8 + g;
            uint4 kq[4];
            #pragma unroll
            for (int grp = 0; grp < 4; grp++)
                kq[grp] = *(const uint4*)&Kb[krow * 72 + grp * 16 + tig * 4];
            s[nt][0] = s[nt][1] = s[nt][2] = s[nt][3] = 0.f;
            #pragma unroll
            for (int ks = 0; ks < 8; ks++) {
                uint32_t b[2] = { uelem(kq[ks >> 1], (ks & 1) * 2),
                                  uelem(kq[ks >> 1], (ks & 1) * 2 + 1) };
                mma8(s[nt], qa[ks], b);
            }
        }

        // ---- per-warp online softmax (regs + shfl over tig) ----
        float pm0 = -1e30f, pm1 = -1e30f;
        #pragma unroll
        for (int nt = 0; nt < 4; nt++) {
            pm0 = fmaxf(pm0, fmaxf(s[nt][0], s[nt][1]));
            pm1 = fmaxf(pm1, fmaxf(s[nt][2], s[nt][3]));
        }
        pm0 = fmaxf(pm0, __shfl_xor_sync(~0u, pm0, 1));
        pm0 = fmaxf(pm0, __shfl_xor_sync(~0u, pm0, 2));
        pm1 = fmaxf(pm1, __shfl_xor_sync(~0u, pm1, 1));
        pm1 = fmaxf(pm1, __shfl_xor_sync(~0u, pm1, 2));
        const float mn0 = fmaxf(m0, pm0), mn1 = fmaxf(m1, pm1);
        const float al0 = __expf(m0 - mn0), al1 = __expf(m1 - mn1);
        m0 = mn0; m1 = mn1;
        float ps0 = 0.f, ps1 = 0.f;
        #pragma unroll
        for (int nt = 0; nt < 4; nt++) {
            s[nt][0] = __expf(s[nt][0] - mn0);
            s[nt][1] = __expf(s[nt][1] - mn0);
            s[nt][2] = __expf(s[nt][2] - mn1);
            s[nt][3] = __expf(s[nt][3] - mn1);
            ps0 += s[nt][0] + s[nt][1];
            ps1 += s[nt][2] + s[nt][3];
        }
        ps0 += __shfl_xor_sync(~0u, ps0, 1); ps0 += __shfl_xor_sync(~0u, ps0, 2);
        ps1 += __shfl_xor_sync(~0u, ps1, 1); ps1 += __shfl_xor_sync(~0u, ps1, 2);
        l0 = l0 * al0 + ps0;
        l1 = l1 * al1 + ps1;
        #pragma unroll
        for (int nt = 0; nt < 4; nt++) {
            oacc[nt][0] *= al0; oacc[nt][1] *= al0;
            oacc[nt][2] *= al1; oacc[nt][3] *= al1;
        }

        // ---- O += P @ V  (P via shfl register transpose) ----
        const int src0 = g * 4 + (tig >> 1);
        const int src2 = src0 + 2;
        const bool hi = (tig & 1);
        #pragma unroll
        for (int grp = 0; grp < 2; grp++) {
            uint4 vq[4];
            #pragma unroll
            for (int nt = 0; nt < 4; nt++)
                vq[nt] = *(const uint4*)&Vb[(nt * 8 + g) * 72 + wn * 32 + grp * 16 + tig * 4];
            #pragma unroll
            for (int h2 = 0; h2 < 2; h2++) {
                const int kc = grp * 2 + h2;
                uint32_t a[4];
                float x, y;
                x = __shfl_sync(~0u, s[kc][0], src0); y = __shfl_sync(~0u, s[kc][1], src0);
                a[0] = f2tf(hi ? y : x);
                x = __shfl_sync(~0u, s[kc][2], src0); y = __shfl_sync(~0u, s[kc][3], src0);
                a[1] = f2tf(hi ? y : x);
                x = __shfl_sync(~0u, s[kc][0], src2); y = __shfl_sync(~0u, s[kc][1], src2);
                a[2] = f2tf(hi ? y : x);
                x = __shfl_sync(~0u, s[kc][2], src2); y = __shfl_sync(~0u, s[kc][3], src2);
                a[3] = f2tf(hi ? y : x);
                #pragma unroll
                for (int nt = 0; nt < 4; nt++) {
                    uint32_t b[2] = { uelem(vq[nt], h2 * 2), uelem(vq[nt], h2 * 2 + 1) };
                    mma8(oacc[nt], a, b);
                }
            }
        }
        __syncthreads();   // all reads of this buffer done before it is re-filled
    }

    // ---- split-K merge of the wn pair ----
    const int r0 = wm * 16 + g;
    if (wn == 0) {
        #pragma unroll
        for (int nt = 0; nt < 4; nt++) {
            const int c = nt * 8 + tig * 2;
            Os[r0 * 36 + c]           = oacc[nt][0];
            Os[r0 * 36 + c + 1]       = oacc[nt][1];
            Os[(r0 + 8) * 36 + c]     = oacc[nt][2];
            Os[(r0 + 8) * 36 + c + 1] = oacc[nt][3];
        }
        if (tig == 0) {
            Ml[r0 * 4 + 0] = m0; Ml[r0 * 4 + 1] = l0;
            Ml[(r0 + 8) * 4 + 0] = m1; Ml[(r0 + 8) * 4 + 1] = l1;
        }
    }
    __syncthreads();
    if (wn == 1) {
        const int b = bh >> 3, h = bh & 7;
        const float mo0 = Ml[r0 * 4 + 0], lo0 = Ml[r0 * 4 + 1];
        const float mo1 = Ml[(r0 + 8) * 4 + 0], lo1 = Ml[(r0 + 8) * 4 + 1];
        const float mg0 = fmaxf(mo0, m0), mg1 = fmaxf(mo1, m1);
        const float so0 = __expf(mo0 - mg0), sw0 = __expf(m0 - mg0);
        const float so1 = __expf(mo1 - mg1), sw1 = __expf(m1 - mg1);
        const float inv0 = 1.f / (lo0 * so0 + l0 * sw0);
        const float inv1 = 1.f / (lo1 * so1 + l1 * sw1);
        const int n0 = q0 + r0, n1 = n0 + 8;
        #pragma unroll
        for (int nt = 0; nt < 4; nt++) {
            const int c = nt * 8 + tig * 2;
            if (n0 < NQ) {
                const size_t base = ((size_t)n0 * BATCH + b) * CDIM + h * DV + c;
                g_Oattn[base]     = (Os[r0 * 36 + c]     * so0 + oacc[nt][0] * sw0) * inv0;
                g_Oattn[base + 1] = (Os[r0 * 36 + c + 1] * so0 + oacc[nt][1] * sw0) * inv0;
            }
            if (n1 < NQ) {
                const size_t base = ((size_t)n1 * BATCH + b) * CDIM + h * DV + c;
                g_Oattn[base]     = (Os[(r0 + 8) * 36 + c]     * so1 + oacc[nt][2] * sw1) * inv1;
                g_Oattn[base + 1] = (Os[(r0 + 8) * 36 + c + 1] * so1 + oacc[nt][3] * sw1) * inv1;
            }
        }
    }
}

// ---------------------------------------------------------------------------
extern "C" void kernel_launch(void* const* d_in, const int* in_sizes, int n_in,
                              void* d_out, int out_size)
{
    const float* query    = (const float*)d_in[0];
    const float* key      = (const float*)d_in[1];
    const float* value    = (const float*)d_in[2];
    const float* querypos = (const float*)d_in[3];
    const float* keypos   = (const float*)d_in[4];
    const float* qsine    = (const float*)d_in[5];
    const float* Wqc = (const float*)d_in[6];  const float* bqc = (const float*)d_in[7];
    const float* Wqp = (const float*)d_in[8];  const float* bqp = (const float*)d_in[9];
    const float* Wqs = (const float*)d_in[10]; const float* bqs = (const float*)d_in[11];
    const float* Wkc = (const float*)d_in[12]; const float* bkc = (const float*)d_in[13];
    const float* Wkp = (const float*)d_in[14]; const float* bkp = (const float*)d_in[15];
    const float* Wv  = (const float*)d_in[16]; const float* bv  = (const float*)d_in[17];
    const float* Wo  = (const float*)d_in[18]; const float* bo  = (const float*)d_in[19];
    float* out = (float*)d_out;

    const int MK = NK * BATCH;   // 16384
    const int MQ = NQ * BATCH;   // 3600
    const dim3 blk(256);
    const dim3 gK(MK / 128, CDIM / 64);
    const dim3 gQ((MQ + 127) / 128, CDIM / 64);

    static bool attr_done = false;
    if (!attr_done) {
        cudaFuncSetAttribute(proj_mma<M_KPC>, cudaFuncAttributeMaxDynamicSharedMemorySize, PROJ_SMEM);
        cudaFuncSetAttribute(proj_mma<M_V>,   cudaFuncAttributeMaxDynamicSharedMemorySize, PROJ_SMEM);
        cudaFuncSetAttribute(proj_mma<M_QALL>,cudaFuncAttributeMaxDynamicSharedMemorySize, PROJ_SMEM);
        cudaFuncSetAttribute(proj_mma<M_OUT>, cudaFuncAttributeMaxDynamicSharedMemorySize, PROJ_SMEM);
        cudaFuncSetAttribute(attn_mma, cudaFuncAttributeMaxDynamicSharedMemorySize, ATT_SMEM_BYTES);
        attr_done = true;
    }

    proj_mma<M_KPC><<<gK, blk, PROJ_SMEM>>>(key, keypos, nullptr,
                                            Wkc, Wkp, nullptr,
                                            bkc, nullptr, bkp,
                                            nullptr, nullptr, MK);
    proj_mma<M_V><<<gK, blk, PROJ_SMEM>>>(value, nullptr, nullptr,
                                          Wv, nullptr, nullptr,
                                          bv, nullptr, nullptr,
                                          nullptr, nullptr, MK);
    proj_mma<M_QALL><<<gQ, blk, PROJ_SMEM>>>(query, querypos, qsine,
                                             Wqc, Wqp, Wqs,
                                             bqc, bqp, bqs,
                                             nullptr, nullptr, MQ);
    attn_mma<<<dim3((NQ + 63) / 64, 32), blk, ATT_SMEM_BYTES>>>();
    proj_mma<M_OUT><<<gQ, blk, PROJ_SMEM>>>(nullptr, nullptr, nullptr,
                                            Wo, nullptr, nullptr,
                                            bo, nullptr, nullptr,
                                            query, out, MQ);
}

// round 6
// speedup vs baseline: 4.5049x; 1.5083x over previous
#include <cuda_runtime.h>
#include <cuda_bf16.h>
#include <cstdint>
#include <cstddef>

// ---------------------------------------------------------------------------
// Conditional-DETR cross attention — TF32 projections + bf16 flash attention.
// ---------------------------------------------------------------------------

#define NQ    900
#define NK    4096
#define BATCH 4
#define CDIM  256
#define NH    8
#define DV    32
#define DQK   64
#define QSCALE 0.125f

// bf16 scratch, fragment-permuted (see pmap):
// K: [bh][key][64]   (head-dim permuted within 32-blocks)
// V: [bh*32+vcol][key] (key permuted within 32-blocks)
// Q: [bh][n][64]     (head-dim permuted, pre-scaled)
__device__ __nv_bfloat16 g_Kcat[(size_t)32 * NK * DQK];
__device__ __nv_bfloat16 g_Vh[(size_t)32 * DV * NK];
__device__ __nv_bfloat16 g_Qcat[(size_t)32 * NQ * DQK];
__device__ float         g_Oattn[(size_t)NQ * BATCH * CDIM]; // [n][b][h*32+v]

#define M_KPC  0
#define M_V    1
#define M_QALL 2
#define M_OUT  3

__device__ __forceinline__ uint32_t f2tf(float f) {
    uint32_t u; asm("cvt.rna.tf32.f32 %0, %1;" : "=r"(u) : "f"(f)); return u;
}
__device__ __forceinline__ uint32_t packbf(float lo, float hi) {
    uint32_t r; asm("cvt.rn.bf16x2.f32 %0, %1, %2;" : "=r"(r) : "f"(hi), "f"(lo));
    return r;
}

__device__ __forceinline__ void mma8(float* d, const uint32_t* a, const uint32_t* b) {
    asm volatile(
        "mma.sync.aligned.m16n8k8.row.col.f32.tf32.tf32.f32 "
        "{%0,%1,%2,%3}, {%4,%5,%6,%7}, {%8,%9}, {%0,%1,%2,%3};"
        : "+f"(d[0]), "+f"(d[1]), "+f"(d[2]), "+f"(d[3])
        : "r"(a[0]), "r"(a[1]), "r"(a[2]), "r"(a[3]), "r"(b[0]), "r"(b[1]));
}
__device__ __forceinline__ void mma16(float* d, const uint32_t* a, const uint32_t* b) {
    asm volatile(
        "mma.sync.aligned.m16n8k16.row.col.f32.bf16.bf16.f32 "
        "{%0,%1,%2,%3}, {%4,%5,%6,%7}, {%8,%9}, {%0,%1,%2,%3};"
        : "+f"(d[0]), "+f"(d[1]), "+f"(d[2]), "+f"(d[3])
        : "r"(a[0]), "r"(a[1]), "r"(a[2]), "r"(a[3]), "r"(b[0]), "r"(b[1]));
}

__device__ __forceinline__ void cpa16(uint32_t dst, const void* src, int sz) {
    asm volatile("cp.async.cg.shared.global [%0], [%1], 16, %2;"
                 :: "r"(dst), "l"(src), "r"(sz));
}
#define CP_COMMIT asm volatile("cp.async.commit_group;" ::: "memory")
#define CP_WAIT0  asm volatile("cp.async.wait_group 0;" ::: "memory")
#define CP_WAIT1  asm volatile("cp.async.wait_group 1;" ::: "memory")

// Fragment permutation within each 32-block: logical x -> slot so a thread's
// 16B load at (tig*8) holds {2t,2t+1,2t+8,2t+9} of chunk0 then chunk1.
__device__ __forceinline__ int pmap(int x) {
    const int pos = x & 15, gg = (x >> 4) & 1;
    return (x & ~31) | (((pos & 7) >> 1) << 3) | (gg << 2) | ((pos >> 3) << 1) | (pos & 1);
}

// ---------------------------------------------------------------------------
// Pipelined TF32 GEMM (unchanged core); epilogues emit permuted bf16.
// ---------------------------------------------------------------------------
#define PROJ_SMEM ((2*128*36 + 2*64*36) * 4)

template<int MODE>
__device__ __forceinline__ void pickAW(int kc,
    const float* A0, const float* A1, const float* A2,
    const float* W0, const float* W1, const float* W2,
    const float*& Ap, const float*& Wp, int& k0)
{
    if (MODE == M_KPC) {
        if (kc < 8) { Ap = A0; Wp = W0; k0 = kc * 32; }
        else        { Ap = A1; Wp = W1; k0 = (kc - 8) * 32; }
    } else if (MODE == M_QALL) {
        if (kc < 8)       { Ap = A0; Wp = W0; k0 = kc * 32; }
        else if (kc < 16) { Ap = A1; Wp = W1; k0 = (kc - 8) * 32; }
        else              { Ap = A2; Wp = W2; k0 = (kc - 16) * 32; }
    } else if (MODE == M_OUT) {
        Ap = g_Oattn; Wp = W0; k0 = kc * 32;
    } else {
        Ap = A0; Wp = W0; k0 = kc * 32;
    }
}

template<int MODE>
__global__ __launch_bounds__(256)
void proj_mma(const float* __restrict__ A0, const float* __restrict__ A1,
              const float* __restrict__ A2,
              const float* __restrict__ W0, const float* __restrict__ W1,
              const float* __restrict__ W2,
              const float* __restrict__ b0a, const float* __restrict__ b0b,
              const float* __restrict__ b1,
              const float* __restrict__ addsrc, float* __restrict__ outp, int M)
{
    extern __shared__ float psm[];
    float* As = psm;
    float* Ws = psm + 2 * 128 * 36;
    const uint32_t asB = (uint32_t)__cvta_generic_to_shared(As);
    const uint32_t wsB = (uint32_t)__cvta_generic_to_shared(Ws);

    const int tid = threadIdx.x;
    const int w = tid >> 5, lane = tid & 31;
    const int g = lane >> 2, tig = lane & 3;
    const int wm = w >> 1, wn = w & 1;
    const int m0 = blockIdx.x * 128;
    const int c0 = blockIdx.y * 64;

    float acc0[2][4][4] = {};
    float acc1[2][4][4] = {};
    const int nchunk = (MODE == M_KPC) ? 16 : (MODE == M_QALL) ? 24 : 8;

    auto load_chunk = [&](int kc, int buf) {
        const float *Ap, *Wp; int k0;
        pickAW<MODE>(kc, A0, A1, A2, W0, W1, W2, Ap, Wp, k0);
        #pragma unroll
        for (int t = 0; t < 4; t++) {
            int i = tid + t * 256;
            int r = i >> 3, s = (i & 7) * 4;
            int row = m0 + r;
            uint32_t dst = asB + (((buf * 128 + r) * 36 + s) << 2);
            cpa16(dst, Ap + (size_t)row * CDIM + k0 + s, row < M ? 16 : 0);
        }
        #pragma unroll
        for (int t = 0; t < 2; t++) {
            int i = tid + t * 256;
            int r = i >> 3, s = (i & 7) * 4;
            uint32_t dst = wsB + (((buf * 64 + r) * 36 + s) << 2);
            cpa16(dst, Wp + (size_t)(c0 + r) * CDIM + k0 + s, 16);
        }
    };

    auto compute = [&](int buf, float (&acc)[2][4][4]) {
        const float* Ab = As + buf * 128 * 36;
        const float* Wb = Ws + buf * 64 * 36;
        #pragma unroll
        for (int ks = 0; ks < 4; ks++) {
            uint32_t a[2][4], b[4][2];
            #pragma unroll
            for (int mt = 0; mt < 2; mt++) {
                int r = wm * 32 + mt * 16 + g;
                a[mt][0] = f2tf(Ab[r * 36 + ks * 8 + tig]);
                a[mt][1] = f2tf(Ab[(r + 8) * 36 + ks * 8 + tig]);
                a[mt][2] = f2tf(Ab[r * 36 + ks * 8 + tig + 4]);
                a[mt][3] = f2tf(Ab[(r + 8) * 36 + ks * 8 + tig + 4]);
            }
            #pragma unroll
            for (int nt = 0; nt < 4; nt++) {
                int c = wn * 32 + nt * 8 + g;
                b[nt][0] = f2tf(Wb[c * 36 + ks * 8 + tig]);
                b[nt][1] = f2tf(Wb[c * 36 + ks * 8 + tig + 4]);
            }
            #pragma unroll
            for (int mt = 0; mt < 2; mt++)
                #pragma unroll
                for (int nt = 0; nt < 4; nt++)
                    mma8(acc[mt][nt], a[mt], b[nt]);
        }
    };

    load_chunk(0, 0);
    CP_COMMIT;
    for (int kc = 0; kc < nchunk; kc++) {
        if (kc + 1 < nchunk) { load_chunk(kc + 1, (kc + 1) & 1); CP_COMMIT; CP_WAIT1; }
        else                 { CP_WAIT0; }
        __syncthreads();
        const bool sec = (MODE == M_KPC && kc >= 8) || (MODE == M_QALL && kc >= 16);
        if (sec) compute(kc & 1, acc1);
        else     compute(kc & 1, acc0);
        __syncthreads();
    }

    #pragma unroll
    for (int mt = 0; mt < 2; mt++)
    #pragma unroll
    for (int nt = 0; nt < 4; nt++)
    #pragma unroll
    for (int cr = 0; cr < 4; cr++) {
        const int row = m0 + wm * 32 + mt * 16 + g + ((cr >= 2) ? 8 : 0);
        if (row >= M) continue;
        const int col = c0 + wn * 32 + nt * 8 + tig * 2 + (cr & 1);

        if (MODE == M_KPC) {
            const int m = row >> 2, b = row & 3, h = col >> 5, ii = col & 31;
            const float vkp = acc1[mt][nt][cr] + b1[col];
            const float vk  = acc0[mt][nt][cr] + b0a[col] + vkp;
            const size_t base = ((size_t)(b * NH + h) * NK + m) * DQK;
            g_Kcat[base + pmap(ii)]      = __float2bfloat16(vk);
            g_Kcat[base + pmap(ii + 32)] = __float2bfloat16(vkp);
        } else if (MODE == M_V) {
            const int m = row >> 2, b = row & 3, h = col >> 5, ii = col & 31;
            g_Vh[((size_t)(b * NH + h) * DV + ii) * NK + (m & ~31) + pmap(m & 31)] =
                __float2bfloat16(acc0[mt][nt][cr] + b0a[col]);
        } else if (MODE == M_QALL) {
            const int n = row >> 2, b = row & 3, h = col >> 5, ii = col & 31;
            const size_t base = ((size_t)(b * NH + h) * NQ + n) * DQK;
            g_Qcat[base + pmap(ii)] =
                __float2bfloat16((acc0[mt][nt][cr] + b0a[col] + b0b[col]) * QSCALE);
            g_Qcat[base + pmap(ii + 32)] =
                __float2bfloat16((acc1[mt][nt][cr] + b1[col]) * QSCALE);
        } else { // M_OUT
            outp[(size_t)row * CDIM + col] =
                addsrc[(size_t)row * CDIM + col] + acc0[mt][nt][cr] + b0a[col];
        }
    }
}

// ---------------------------------------------------------------------------
// bf16 flash attention, register split-K. 8 warps: wm 0..3 (16 q-rows each),
// wn 0..1 (32-key strips). Row stride 96 bf16 (192B) = conflict-free LDS.128.
// ---------------------------------------------------------------------------
#define ATT_Q_OFF   0
#define ATT_K_OFF   (64 * 96)
#define ATT_V_OFF   (ATT_K_OFF + 2 * 64 * 96)
#define ATT_SMEM_BYTES ((ATT_V_OFF + 2 * 32 * 96) * 2)     // 48 KB

__global__ __launch_bounds__(256, 2)
void attn_mma()
{
    extern __shared__ __nv_bfloat16 smb[];
    __nv_bfloat16* Qs = smb + ATT_Q_OFF;
    __nv_bfloat16* Ks = smb + ATT_K_OFF;
    __nv_bfloat16* Vs = smb + ATT_V_OFF;
    float* Os = (float*)Ks;                // epilogue reuse [64][36] (24KB avail)
    float* Ml = (float*)Vs;                // epilogue reuse [64][4]
    const uint32_t qsB = (uint32_t)__cvta_generic_to_shared(Qs);
    const uint32_t ksB = (uint32_t)__cvta_generic_to_shared(Ks);
    const uint32_t vsB = (uint32_t)__cvta_generic_to_shared(Vs);

    const int tid = threadIdx.x;
    const int w = tid >> 5, lane = tid & 31;
    const int g = lane >> 2, tig = lane & 3;
    const int wm = w >> 1, wn = w & 1;
    const int bh = blockIdx.y;
    const int q0 = blockIdx.x * 64;

    auto issueQ = [&]() {
        #pragma unroll
        for (int t = 0; t < 2; t++) {
            int i = tid + t * 256;         // 0..511 : 64 rows x 8 chunks
            int r = i >> 3, c8 = i & 7;
            int n = q0 + r;
            uint32_t dst = qsB + (r * 96 + c8 * 8) * 2;
            cpa16(dst, &g_Qcat[((size_t)bh * NQ + (n < NQ ? n : 0)) * DQK + c8 * 8],
                  n < NQ ? 16 : 0);
        }
    };
    auto issueKV = [&](int kt, int buf) {
        const int mbase = kt * 64;
        #pragma unroll
        for (int t = 0; t < 2; t++) {
            int i = tid + t * 256;
            int r = i >> 3, c8 = i & 7;
            uint32_t dst = ksB + ((buf * 64 + r) * 96 + c8 * 8) * 2;
            cpa16(dst, &g_Kcat[((size_t)bh * NK + mbase + r) * DQK + c8 * 8], 16);
        }
        {
            int r = tid >> 3, c8 = tid & 7;
            uint32_t dst = vsB + ((buf * 32 + r) * 96 + c8 * 8) * 2;
            cpa16(dst, &g_Vh[((size_t)bh * DV + r) * NK + mbase + c8 * 8], 16);
        }
    };

    issueQ();
    issueKV(0, 0);
    CP_COMMIT;

    uint32_t qa[4][4];              // Q fragments for 4 head-dim chunks
    float oacc[4][4] = {};          // rows {g,g+8} x vcols {nt*8+2tig,+1}
    float m0 = -1e30f, m1 = -1e30f, l0 = 0.f, l1 = 0.f;

    const int NT = NK / 64;
    for (int kt = 0; kt < NT; kt++) {
        const int buf = kt & 1;
        if (kt + 1 < NT) { issueKV(kt + 1, buf ^ 1); CP_COMMIT; CP_WAIT1; }
        else             { CP_WAIT0; }
        __syncthreads();

        if (kt == 0) {   // hoist Q fragments
            const int r = wm * 16 + g;
            #pragma unroll
            for (int p = 0; p < 2; p++) {
                uint4 ug  = *(const uint4*)(Qs + r * 96 + p * 32 + tig * 8);
                uint4 ug8 = *(const uint4*)(Qs + (r + 8) * 96 + p * 32 + tig * 8);
                qa[2*p][0]   = ug.x; qa[2*p][1]   = ug8.x;
                qa[2*p][2]   = ug.y; qa[2*p][3]   = ug8.y;
                qa[2*p+1][0] = ug.z; qa[2*p+1][1] = ug8.z;
                qa[2*p+1][2] = ug.w; qa[2*p+1][3] = ug8.w;
            }
        }

        const __nv_bfloat16* Kb = Ks + buf * 64 * 96;
        const __nv_bfloat16* Vb = Vs + buf * 32 * 96;

        // ---- S = Q @ K^T over this warp's 32-key strip ----
        float s[4][4];
        #pragma unroll
        for (int nt = 0; nt < 4; nt++) {
            const int krow = wn * 32 + nt * 8 + g;
            uint4 kq0 = *(const uint4*)(Kb + krow * 96 + tig * 8);
            uint4 kq1 = *(const uint4*)(Kb + krow * 96 + 32 + tig * 8);
            s[nt][0] = s[nt][1] = s[nt][2] = s[nt][3] = 0.f;
            { uint32_t b[2] = {kq0.x, kq0.y}; mma16(s[nt], qa[0], b); }
            { uint32_t b[2] = {kq0.z, kq0.w}; mma16(s[nt], qa[1], b); }
            { uint32_t b[2] = {kq1.x, kq1.y}; mma16(s[nt], qa[2], b); }
            { uint32_t b[2] = {kq1.z, kq1.w}; mma16(s[nt], qa[3], b); }
        }

        // ---- per-warp online softmax (regs + shfl over tig) ----
        float pm0 = -1e30f, pm1 = -1e30f;
        #pragma unroll
        for (int nt = 0; nt < 4; nt++) {
            pm0 = fmaxf(pm0, fmaxf(s[nt][0], s[nt][1]));
            pm1 = fmaxf(pm1, fmaxf(s[nt][2], s[nt][3]));
        }
        pm0 = fmaxf(pm0, __shfl_xor_sync(~0u, pm0, 1));
        pm0 = fmaxf(pm0, __shfl_xor_sync(~0u, pm0, 2));
        pm1 = fmaxf(pm1, __shfl_xor_sync(~0u, pm1, 1));
        pm1 = fmaxf(pm1, __shfl_xor_sync(~0u, pm1, 2));
        const float mn0 = fmaxf(m0, pm0), mn1 = fmaxf(m1, pm1);
        const float al0 = __expf(m0 - mn0), al1 = __expf(m1 - mn1);
        m0 = mn0; m1 = mn1;
        float ps0 = 0.f, ps1 = 0.f;
        #pragma unroll
        for (int nt = 0; nt < 4; nt++) {
            s[nt][0] = __expf(s[nt][0] - mn0);
            s[nt][1] = __expf(s[nt][1] - mn0);
            s[nt][2] = __expf(s[nt][2] - mn1);
            s[nt][3] = __expf(s[nt][3] - mn1);
            ps0 += s[nt][0] + s[nt][1];
            ps1 += s[nt][2] + s[nt][3];
        }
        ps0 += __shfl_xor_sync(~0u, ps0, 1); ps0 += __shfl_xor_sync(~0u, ps0, 2);
        ps1 += __shfl_xor_sync(~0u, ps1, 1); ps1 += __shfl_xor_sync(~0u, ps1, 2);
        l0 = l0 * al0 + ps0;
        l1 = l1 * al1 + ps1;
        #pragma unroll
        for (int nt = 0; nt < 4; nt++) {
            oacc[nt][0] *= al0; oacc[nt][1] *= al0;
            oacc[nt][2] *= al1; oacc[nt][3] *= al1;
        }

        // ---- O += P @ V (P packs directly into A-fragments; no shuffles) ----
        uint4 vq[4];
        #pragma unroll
        for (int nt = 0; nt < 4; nt++)
            vq[nt] = *(const uint4*)(Vb + (nt * 8 + g) * 96 + wn * 32 + tig * 8);
        #pragma unroll
        for (int c = 0; c < 2; c++) {
            uint32_t a[4];
            a[0] = packbf(s[2*c][0],   s[2*c][1]);
            a[1] = packbf(s[2*c][2],   s[2*c][3]);
            a[2] = packbf(s[2*c+1][0], s[2*c+1][1]);
            a[3] = packbf(s[2*c+1][2], s[2*c+1][3]);
            #pragma unroll
            for (int nt = 0; nt < 4; nt++) {
                uint32_t b[2] = { c ? vq[nt].z : vq[nt].x,
                                  c ? vq[nt].w : vq[nt].y };
                mma16(oacc[nt], a, b);
            }
        }
        __syncthreads();   // buffer reads done before refill
    }

    // ---- split-K merge of the wn pair ----
    const int r0 = wm * 16 + g;
    if (wn == 0) {
        #pragma unroll
        for (int nt = 0; nt < 4; nt++) {
            const int c = nt * 8 + tig * 2;
            Os[r0 * 36 + c]           = oacc[nt][0];
            Os[r0 * 36 + c + 1]       = oacc[nt][1];
            Os[(r0 + 8) * 36 + c]     = oacc[nt][2];
            Os[(r0 + 8) * 36 + c + 1] = oacc[nt][3];
        }
        if (tig == 0) {
            Ml[r0 * 4 + 0] = m0; Ml[r0 * 4 + 1] = l0;
            Ml[(r0 + 8) * 4 + 0] = m1; Ml[(r0 + 8) * 4 + 1] = l1;
        }
    }
    __syncthreads();
    if (wn == 1) {
        const int b = bh >> 3, h = bh & 7;
        const float mo0 = Ml[r0 * 4 + 0], lo0 = Ml[r0 * 4 + 1];
        const float mo1 = Ml[(r0 + 8) * 4 + 0], lo1 = Ml[(r0 + 8) * 4 + 1];
        const float mg0 = fmaxf(mo0, m0), mg1 = fmaxf(mo1, m1);
        const float so0 = __expf(mo0 - mg0), sw0 = __expf(m0 - mg0);
        const float so1 = __expf(mo1 - mg1), sw1 = __expf(m1 - mg1);
        const float inv0 = 1.f / (lo0 * so0 + l0 * sw0);
        const float inv1 = 1.f / (lo1 * so1 + l1 * sw1);
        const int n0 = q0 + r0, n1 = n0 + 8;
        #pragma unroll
        for (int nt = 0; nt < 4; nt++) {
            const int c = nt * 8 + tig * 2;
            if (n0 < NQ) {
                const size_t base = ((size_t)n0 * BATCH + b) * CDIM + h * DV + c;
                g_Oattn[base]     = (Os[r0 * 36 + c]     * so0 + oacc[nt][0] * sw0) * inv0;
                g_Oattn[base + 1] = (Os[r0 * 36 + c + 1] * so0 + oacc[nt][1] * sw0) * inv0;
            }
            if (n1 < NQ) {
                const size_t base = ((size_t)n1 * BATCH + b) * CDIM + h * DV + c;
                g_Oattn[base]     = (Os[(r0 + 8) * 36 + c]     * so1 + oacc[nt][2] * sw1) * inv1;
                g_Oattn[base + 1] = (Os[(r0 + 8) * 36 + c + 1] * so1 + oacc[nt][3] * sw1) * inv1;
            }
        }
    }
}

// ---------------------------------------------------------------------------
extern "C" void kernel_launch(void* const* d_in, const int* in_sizes, int n_in,
                              void* d_out, int out_size)
{
    const float* query    = (const float*)d_in[0];
    const float* key      = (const float*)d_in[1];
    const float* value    = (const float*)d_in[2];
    const float* querypos = (const float*)d_in[3];
    const float* keypos   = (const float*)d_in[4];
    const float* qsine    = (const float*)d_in[5];
    const float* Wqc = (const float*)d_in[6];  const float* bqc = (const float*)d_in[7];
    const float* Wqp = (const float*)d_in[8];  const float* bqp = (const float*)d_in[9];
    const float* Wqs = (const float*)d_in[10]; const float* bqs = (const float*)d_in[11];
    const float* Wkc = (const float*)d_in[12]; const float* bkc = (const float*)d_in[13];
    const float* Wkp = (const float*)d_in[14]; const float* bkp = (const float*)d_in[15];
    const float* Wv  = (const float*)d_in[16]; const float* bv  = (const float*)d_in[17];
    const float* Wo  = (const float*)d_in[18]; const float* bo  = (const float*)d_in[19];
    float* out = (float*)d_out;

    const int MK = NK * BATCH;   // 16384
    const int MQ = NQ * BATCH;   // 3600
    const dim3 blk(256);
    const dim3 gK(MK / 128, CDIM / 64);
    const dim3 gQ((MQ + 127) / 128, CDIM / 64);

    static bool attr_done = false;
    if (!attr_done) {
        cudaFuncSetAttribute(proj_mma<M_KPC>, cudaFuncAttributeMaxDynamicSharedMemorySize, PROJ_SMEM);
        cudaFuncSetAttribute(proj_mma<M_V>,   cudaFuncAttributeMaxDynamicSharedMemorySize, PROJ_SMEM);
        cudaFuncSetAttribute(proj_mma<M_QALL>,cudaFuncAttributeMaxDynamicSharedMemorySize, PROJ_SMEM);
        cudaFuncSetAttribute(proj_mma<M_OUT>, cudaFuncAttributeMaxDynamicSharedMemorySize, PROJ_SMEM);
        cudaFuncSetAttribute(attn_mma, cudaFuncAttributeMaxDynamicSharedMemorySize, ATT_SMEM_BYTES);
        attr_done = true;
    }

    proj_mma<M_KPC><<<gK, blk, PROJ_SMEM>>>(key, keypos, nullptr,
                                            Wkc, Wkp, nullptr,
                                            bkc, nullptr, bkp,
                                            nullptr, nullptr, MK);
    proj_mma<M_V><<<gK, blk, PROJ_SMEM>>>(value, nullptr, nullptr,
                                          Wv, nullptr, nullptr,
                                          bv, nullptr, nullptr,
                                          nullptr, nullptr, MK);
    proj_mma<M_QALL><<<gQ, blk, PROJ_SMEM>>>(query, querypos, qsine,
                                             Wqc, Wqp, Wqs,
                                             bqc, bqp, bqs,
                                             nullptr, nullptr, MQ);
    attn_mma<<<dim3((NQ + 63) / 64, 32), blk, ATT_SMEM_BYTES>>>();
    proj_mma<M_OUT><<<gQ, blk, PROJ_SMEM>>>(nullptr, nullptr, nullptr,
                                            Wo, nullptr, nullptr,
                                            bo, nullptr, nullptr,
                                            query, out, MQ);
}

// round 7
// speedup vs baseline: 5.2430x; 1.1638x over previous
#include <cuda_runtime.h>
#include <cuda_bf16.h>
#include <cstdint>
#include <cstddef>

// ---------------------------------------------------------------------------
// Conditional-DETR cross attention — TF32 proj (fused) + bf16 flash attention.
// ---------------------------------------------------------------------------

#define NQ    900
#define NK    4096
#define BATCH 4
#define CDIM  256
#define NH    8
#define DV    32
#define DQK   64
// 0.125 * log2(e): softmax done in exp2 domain
#define QSCALE_L2E 0.1803368801111204f

__device__ __nv_bfloat16 g_Kcat[(size_t)32 * NK * DQK];
__device__ __nv_bfloat16 g_Vh[(size_t)32 * DV * NK];
__device__ __nv_bfloat16 g_Qcat[(size_t)32 * NQ * DQK];
__device__ float         g_Oattn[(size_t)NQ * BATCH * CDIM]; // [n][b][h*32+v]

#define M_KPC  0
#define M_V    1
#define M_QALL 2
#define M_OUT  3

__device__ __forceinline__ uint32_t f2tf(float f) {
    uint32_t u; asm("cvt.rna.tf32.f32 %0, %1;" : "=r"(u) : "f"(f)); return u;
}
__device__ __forceinline__ uint32_t packbf(float lo, float hi) {
    uint32_t r; asm("cvt.rn.bf16x2.f32 %0, %1, %2;" : "=r"(r) : "f"(hi), "f"(lo));
    return r;
}
__device__ __forceinline__ float ex2(float x) {
    float r; asm("ex2.approx.ftz.f32 %0, %1;" : "=f"(r) : "f"(x)); return r;
}

__device__ __forceinline__ void mma8(float* d, const uint32_t* a, const uint32_t* b) {
    asm volatile(
        "mma.sync.aligned.m16n8k8.row.col.f32.tf32.tf32.f32 "
        "{%0,%1,%2,%3}, {%4,%5,%6,%7}, {%8,%9}, {%0,%1,%2,%3};"
        : "+f"(d[0]), "+f"(d[1]), "+f"(d[2]), "+f"(d[3])
        : "r"(a[0]), "r"(a[1]), "r"(a[2]), "r"(a[3]), "r"(b[0]), "r"(b[1]));
}
__device__ __forceinline__ void mma16(float* d, const uint32_t* a, const uint32_t* b) {
    asm volatile(
        "mma.sync.aligned.m16n8k16.row.col.f32.bf16.bf16.f32 "
        "{%0,%1,%2,%3}, {%4,%5,%6,%7}, {%8,%9}, {%0,%1,%2,%3};"
        : "+f"(d[0]), "+f"(d[1]), "+f"(d[2]), "+f"(d[3])
        : "r"(a[0]), "r"(a[1]), "r"(a[2]), "r"(a[3]), "r"(b[0]), "r"(b[1]));
}

__device__ __forceinline__ void cpa16(uint32_t dst, const void* src, int sz) {
    asm volatile("cp.async.cg.shared.global [%0], [%1], 16, %2;"
                 :: "r"(dst), "l"(src), "r"(sz));
}
#define CP_COMMIT asm volatile("cp.async.commit_group;" ::: "memory")
#define CP_WAIT0  asm volatile("cp.async.wait_group 0;" ::: "memory")

// fragment permutation within each 32-block (see round 6)
__device__ __forceinline__ int pmap(int x) {
    const int pos = x & 15, gg = (x >> 4) & 1;
    return (x & ~31) | (((pos & 7) >> 1) << 3) | (gg << 2) | ((pos >> 3) << 1) | (pos & 1);
}

// ---------------------------------------------------------------------------
// TF32 projection GEMM body (device fn). Tile 128x64, BK=32, 8 warps.
// One __syncthreads per chunk.
// ---------------------------------------------------------------------------
#define PROJ_SMEM ((2*128*36 + 2*64*36) * 4)

template<int MODE>
__device__ __forceinline__ void pickAW(int kc,
    const float* A0, const float* A1, const float* A2,
    const float* W0, const float* W1, const float* W2,
    const float* oattn,
    const float*& Ap, const float*& Wp, int& k0)
{
    if (MODE == M_KPC) {
        if (kc < 8) { Ap = A0; Wp = W0; k0 = kc * 32; }
        else        { Ap = A1; Wp = W1; k0 = (kc - 8) * 32; }
    } else if (MODE == M_QALL) {
        if (kc < 8)       { Ap = A0; Wp = W0; k0 = kc * 32; }
        else if (kc < 16) { Ap = A1; Wp = W1; k0 = (kc - 8) * 32; }
        else              { Ap = A2; Wp = W2; k0 = (kc - 16) * 32; }
    } else if (MODE == M_OUT) {
        Ap = oattn; Wp = W0; k0 = kc * 32;
    } else {
        Ap = A0; Wp = W0; k0 = kc * 32;
    }
}

template<int MODE>
__device__ __forceinline__ void proj_body(
    int bx, int by,
    const float* __restrict__ A0, const float* __restrict__ A1,
    const float* __restrict__ A2,
    const float* __restrict__ W0, const float* __restrict__ W1,
    const float* __restrict__ W2,
    const float* __restrict__ b0a, const float* __restrict__ b0b,
    const float* __restrict__ b1,
    const float* __restrict__ addsrc, float* __restrict__ outp, int M)
{
    extern __shared__ float psm[];
    float* As = psm;
    float* Ws = psm + 2 * 128 * 36;
    const uint32_t asB = (uint32_t)__cvta_generic_to_shared(As);
    const uint32_t wsB = (uint32_t)__cvta_generic_to_shared(Ws);

    const int tid = threadIdx.x;
    const int w = tid >> 5, lane = tid & 31;
    const int g = lane >> 2, tig = lane & 3;
    const int wm = w >> 1, wn = w & 1;
    const int m0 = bx * 128;
    const int c0 = by * 64;

    float acc0[2][4][4] = {};
    float acc1[2][4][4] = {};
    const int nchunk = (MODE == M_KPC) ? 16 : (MODE == M_QALL) ? 24 : 8;

    auto load_chunk = [&](int kc, int buf) {
        const float *Ap, *Wp; int k0;
        pickAW<MODE>(kc, A0, A1, A2, W0, W1, W2, g_Oattn, Ap, Wp, k0);
        #pragma unroll
        for (int t = 0; t < 4; t++) {
            int i = tid + t * 256;
            int r = i >> 3, s = (i & 7) * 4;
            int row = m0 + r;
            uint32_t dst = asB + (((buf * 128 + r) * 36 + s) << 2);
            cpa16(dst, Ap + (size_t)row * CDIM + k0 + s, row < M ? 16 : 0);
        }
        #pragma unroll
        for (int t = 0; t < 2; t++) {
            int i = tid + t * 256;
            int r = i >> 3, s = (i & 7) * 4;
            uint32_t dst = wsB + (((buf * 64 + r) * 36 + s) << 2);
            cpa16(dst, Wp + (size_t)(c0 + r) * CDIM + k0 + s, 16);
        }
    };

    auto compute = [&](int buf, float (&acc)[2][4][4]) {
        const float* Ab = As + buf * 128 * 36;
        const float* Wb = Ws + buf * 64 * 36;
        #pragma unroll
        for (int ks = 0; ks < 4; ks++) {
            uint32_t a[2][4], b[4][2];
            #pragma unroll
            for (int mt = 0; mt < 2; mt++) {
                int r = wm * 32 + mt * 16 + g;
                a[mt][0] = f2tf(Ab[r * 36 + ks * 8 + tig]);
                a[mt][1] = f2tf(Ab[(r + 8) * 36 + ks * 8 + tig]);
                a[mt][2] = f2tf(Ab[r * 36 + ks * 8 + tig + 4]);
                a[mt][3] = f2tf(Ab[(r + 8) * 36 + ks * 8 + tig + 4]);
            }
            #pragma unroll
            for (int nt = 0; nt < 4; nt++) {
                int c = wn * 32 + nt * 8 + g;
                b[nt][0] = f2tf(Wb[c * 36 + ks * 8 + tig]);
                b[nt][1] = f2tf(Wb[c * 36 + ks * 8 + tig + 4]);
            }
            #pragma unroll
            for (int mt = 0; mt < 2; mt++)
                #pragma unroll
                for (int nt = 0; nt < 4; nt++)
                    mma8(acc[mt][nt], a[mt], b[nt]);
        }
    };

    load_chunk(0, 0);
    CP_COMMIT;
    CP_WAIT0;
    __syncthreads();
    for (int kc = 0; kc < nchunk; kc++) {
        if (kc + 1 < nchunk) { load_chunk(kc + 1, (kc + 1) & 1); CP_COMMIT; }
        const bool sec = (MODE == M_KPC && kc >= 8) || (MODE == M_QALL && kc >= 16);
        if (sec) compute(kc & 1, acc1);
        else     compute(kc & 1, acc0);
        if (kc + 1 < nchunk) { CP_WAIT0; __syncthreads(); }
    }

    #pragma unroll
    for (int mt = 0; mt < 2; mt++)
    #pragma unroll
    for (int nt = 0; nt < 4; nt++)
    #pragma unroll
    for (int cr = 0; cr < 4; cr++) {
        const int row = m0 + wm * 32 + mt * 16 + g + ((cr >= 2) ? 8 : 0);
        if (row >= M) continue;
        const int col = c0 + wn * 32 + nt * 8 + tig * 2 + (cr & 1);

        if (MODE == M_KPC) {
            const int m = row >> 2, b = row & 3, h = col >> 5, ii = col & 31;
            const float vkp = acc1[mt][nt][cr] + b1[col];
            const float vk  = acc0[mt][nt][cr] + b0a[col] + vkp;
            const size_t base = ((size_t)(b * NH + h) * NK + m) * DQK;
            g_Kcat[base + pmap(ii)]      = __float2bfloat16(vk);
            g_Kcat[base + pmap(ii + 32)] = __float2bfloat16(vkp);
        } else if (MODE == M_V) {
            const int m = row >> 2, b = row & 3, h = col >> 5, ii = col & 31;
            g_Vh[((size_t)(b * NH + h) * DV + ii) * NK + (m & ~31) + pmap(m & 31)] =
                __float2bfloat16(acc0[mt][nt][cr] + b0a[col]);
        } else if (MODE == M_QALL) {
            const int n = row >> 2, b = row & 3, h = col >> 5, ii = col & 31;
            const size_t base = ((size_t)(b * NH + h) * NQ + n) * DQK;
            g_Qcat[base + pmap(ii)] =
                __float2bfloat16((acc0[mt][nt][cr] + b0a[col] + b0b[col]) * QSCALE_L2E);
            g_Qcat[base + pmap(ii + 32)] =
                __float2bfloat16((acc1[mt][nt][cr] + b1[col]) * QSCALE_L2E);
        } else { // M_OUT
            outp[(size_t)row * CDIM + col] =
                addsrc[(size_t)row * CDIM + col] + acc0[mt][nt][cr] + b0a[col];
        }
    }
}

// horizontally fused: KPC (512 blocks) | V (512) | QALL (116)
__global__ __launch_bounds__(256)
void proj_fused(const float* __restrict__ key, const float* __restrict__ keypos,
                const float* __restrict__ value,
                const float* __restrict__ query, const float* __restrict__ querypos,
                const float* __restrict__ qsine,
                const float* __restrict__ Wkc, const float* __restrict__ Wkp,
                const float* __restrict__ Wv,
                const float* __restrict__ Wqc, const float* __restrict__ Wqp,
                const float* __restrict__ Wqs,
                const float* __restrict__ bkc, const float* __restrict__ bkp,
                const float* __restrict__ bv,
                const float* __restrict__ bqc, const float* __restrict__ bqp,
                const float* __restrict__ bqs)
{
    int id = blockIdx.x;
    if (id < 512) {
        proj_body<M_KPC>(id & 127, id >> 7, key, keypos, nullptr,
                         Wkc, Wkp, nullptr, bkc, nullptr, bkp,
                         nullptr, nullptr, NK * BATCH);
    } else if (id < 1024) {
        id -= 512;
        proj_body<M_V>(id & 127, id >> 7, value, nullptr, nullptr,
                       Wv, nullptr, nullptr, bv, nullptr, nullptr,
                       nullptr, nullptr, NK * BATCH);
    } else {
        id -= 1024;
        proj_body<M_QALL>(id % 29, id / 29, query, querypos, qsine,
                          Wqc, Wqp, Wqs, bqc, bqp, bqs,
                          nullptr, nullptr, NQ * BATCH);
    }
}

__global__ __launch_bounds__(256)
void proj_out(const float* __restrict__ Wo, const float* __restrict__ bo,
              const float* __restrict__ addsrc, float* __restrict__ outp)
{
    proj_body<M_OUT>(blockIdx.x, blockIdx.y, nullptr, nullptr, nullptr,
                     Wo, nullptr, nullptr, bo, nullptr, nullptr,
                     addsrc, outp, NQ * BATCH);
}

// ---------------------------------------------------------------------------
// bf16 flash attention, register split-K, one barrier per 64-key tile.
// ---------------------------------------------------------------------------
#define ATT_Q_OFF   0
#define ATT_K_OFF   (64 * 96)
#define ATT_V_OFF   (ATT_K_OFF + 2 * 64 * 96)
#define ATT_SMEM_BYTES ((ATT_V_OFF + 2 * 32 * 96) * 2)     // 48 KB

__global__ __launch_bounds__(256, 2)
void attn_mma()
{
    extern __shared__ __nv_bfloat16 smb[];
    __nv_bfloat16* Qs = smb + ATT_Q_OFF;
    __nv_bfloat16* Ks = smb + ATT_K_OFF;
    __nv_bfloat16* Vs = smb + ATT_V_OFF;
    float* Os = (float*)Ks;                // epilogue reuse
    float* Ml = (float*)Vs;                // epilogue reuse
    const uint32_t qsB = (uint32_t)__cvta_generic_to_shared(Qs);
    const uint32_t ksB = (uint32_t)__cvta_generic_to_shared(Ks);
    const uint32_t vsB = (uint32_t)__cvta_generic_to_shared(Vs);

    const int tid = threadIdx.x;
    const int w = tid >> 5, lane = tid & 31;
    const int g = lane >> 2, tig = lane & 3;
    const int wm = w >> 1, wn = w & 1;
    const int bh = blockIdx.y;
    const int q0 = blockIdx.x * 64;

    auto issueQ = [&]() {
        #pragma unroll
        for (int t = 0; t < 2; t++) {
            int i = tid + t * 256;
            int r = i >> 3, c8 = i & 7;
            int n = q0 + r;
            uint32_t dst = qsB + (r * 96 + c8 * 8) * 2;
            cpa16(dst, &g_Qcat[((size_t)bh * NQ + (n < NQ ? n : 0)) * DQK + c8 * 8],
                  n < NQ ? 16 : 0);
        }
    };
    auto issueKV = [&](int kt, int buf) {
        const int mbase = kt * 64;
        #pragma unroll
        for (int t = 0; t < 2; t++) {
            int i = tid + t * 256;
            int r = i >> 3, c8 = i & 7;
            uint32_t dst = ksB + ((buf * 64 + r) * 96 + c8 * 8) * 2;
            cpa16(dst, &g_Kcat[((size_t)bh * NK + mbase + r) * DQK + c8 * 8], 16);
        }
        {
            int r = tid >> 3, c8 = tid & 7;
            uint32_t dst = vsB + ((buf * 32 + r) * 96 + c8 * 8) * 2;
            cpa16(dst, &g_Vh[((size_t)bh * DV + r) * NK + mbase + c8 * 8], 16);
        }
    };

    issueQ();
    issueKV(0, 0);
    CP_COMMIT;

    // per-warp fragment base pointers (constant across loop)
    const __nv_bfloat16* kbase = Ks + (wn * 32 + g) * 96 + tig * 8;
    const __nv_bfloat16* vbase = Vs + g * 96 + wn * 32 + tig * 8;

    uint32_t qa[4][4];
    float oacc[4][4] = {};
    float m0 = -1e30f, m1 = -1e30f, l0 = 0.f, l1 = 0.f;

    CP_WAIT0;
    __syncthreads();

    {   // hoist Q fragments
        const int r = wm * 16 + g;
        #pragma unroll
        for (int p = 0; p < 2; p++) {
            uint4 ug  = *(const uint4*)(Qs + r * 96 + p * 32 + tig * 8);
            uint4 ug8 = *(const uint4*)(Qs + (r + 8) * 96 + p * 32 + tig * 8);
            qa[2*p][0]   = ug.x; qa[2*p][1]   = ug8.x;
            qa[2*p][2]   = ug.y; qa[2*p][3]   = ug8.y;
            qa[2*p+1][0] = ug.z; qa[2*p+1][1] = ug8.z;
            qa[2*p+1][2] = ug.w; qa[2*p+1][3] = ug8.w;
        }
    }

    const int NT = NK / 64;
    for (int kt = 0; kt < NT; kt++) {
        const int buf = kt & 1;
        if (kt + 1 < NT) { issueKV(kt + 1, buf ^ 1); CP_COMMIT; }

        const __nv_bfloat16* Kb = kbase + buf * (64 * 96);
        const __nv_bfloat16* Vb = vbase + buf * (32 * 96);

        // ---- S = Q @ K^T over this warp's 32-key strip ----
        float s[4][4];
        #pragma unroll
        for (int nt = 0; nt < 4; nt++) {
            uint4 kq0 = *(const uint4*)(Kb + nt * (8 * 96));
            uint4 kq1 = *(const uint4*)(Kb + nt * (8 * 96) + 32);
            s[nt][0] = s[nt][1] = s[nt][2] = s[nt][3] = 0.f;
            { uint32_t b[2] = {kq0.x, kq0.y}; mma16(s[nt], qa[0], b); }
            { uint32_t b[2] = {kq0.z, kq0.w}; mma16(s[nt], qa[1], b); }
            { uint32_t b[2] = {kq1.x, kq1.y}; mma16(s[nt], qa[2], b); }
            { uint32_t b[2] = {kq1.z, kq1.w}; mma16(s[nt], qa[3], b); }
        }

        // ---- per-warp online softmax (exp2 domain) ----
        float pm0 = -1e30f, pm1 = -1e30f;
        #pragma unroll
        for (int nt = 0; nt < 4; nt++) {
            pm0 = fmaxf(pm0, fmaxf(s[nt][0], s[nt][1]));
            pm1 = fmaxf(pm1, fmaxf(s[nt][2], s[nt][3]));
        }
        pm0 = fmaxf(pm0, __shfl_xor_sync(~0u, pm0, 1));
        pm0 = fmaxf(pm0, __shfl_xor_sync(~0u, pm0, 2));
        pm1 = fmaxf(pm1, __shfl_xor_sync(~0u, pm1, 1));
        pm1 = fmaxf(pm1, __shfl_xor_sync(~0u, pm1, 2));
        const float mn0 = fmaxf(m0, pm0), mn1 = fmaxf(m1, pm1);
        const float al0 = ex2(m0 - mn0), al1 = ex2(m1 - mn1);
        m0 = mn0; m1 = mn1;
        float ps0 = 0.f, ps1 = 0.f;
        #pragma unroll
        for (int nt = 0; nt < 4; nt++) {
            s[nt][0] = ex2(s[nt][0] - mn0);
            s[nt][1] = ex2(s[nt][1] - mn0);
            s[nt][2] = ex2(s[nt][2] - mn1);
            s[nt][3] = ex2(s[nt][3] - mn1);
            ps0 += s[nt][0] + s[nt][1];
            ps1 += s[nt][2] + s[nt][3];
        }
        ps0 += __shfl_xor_sync(~0u, ps0, 1); ps0 += __shfl_xor_sync(~0u, ps0, 2);
        ps1 += __shfl_xor_sync(~0u, ps1, 1); ps1 += __shfl_xor_sync(~0u, ps1, 2);
        l0 = l0 * al0 + ps0;
        l1 = l1 * al1 + ps1;
        #pragma unroll
        for (int nt = 0; nt < 4; nt++) {
            oacc[nt][0] *= al0; oacc[nt][1] *= al0;
            oacc[nt][2] *= al1; oacc[nt][3] *= al1;
        }

        // ---- O += P @ V (no shuffles; P packs into A-frags) ----
        uint4 vq[4];
        #pragma unroll
        for (int nt = 0; nt < 4; nt++)
            vq[nt] = *(const uint4*)(Vb + nt * (8 * 96));
        #pragma unroll
        for (int c = 0; c < 2; c++) {
            uint32_t a[4];
            a[0] = packbf(s[2*c][0],   s[2*c][1]);
            a[1] = packbf(s[2*c][2],   s[2*c][3]);
            a[2] = packbf(s[2*c+1][0], s[2*c+1][1]);
            a[3] = packbf(s[2*c+1][2], s[2*c+1][3]);
            #pragma unroll
            for (int nt = 0; nt < 4; nt++) {
                uint32_t b[2] = { c ? vq[nt].z : vq[nt].x,
                                  c ? vq[nt].w : vq[nt].y };
                mma16(oacc[nt], a, b);
            }
        }

        if (kt + 1 < NT) { CP_WAIT0; __syncthreads(); }
    }

    __syncthreads();   // all warps done with K/V smem before epilogue reuse

    // ---- split-K merge of the wn pair ----
    const int r0 = wm * 16 + g;
    if (wn == 0) {
        #pragma unroll
        for (int nt = 0; nt < 4; nt++) {
            const int c = nt * 8 + tig * 2;
            Os[r0 * 36 + c]           = oacc[nt][0];
            Os[r0 * 36 + c + 1]       = oacc[nt][1];
            Os[(r0 + 8) * 36 + c]     = oacc[nt][2];
            Os[(r0 + 8) * 36 + c + 1] = oacc[nt][3];
        }
        if (tig == 0) {
            Ml[r0 * 4 + 0] = m0; Ml[r0 * 4 + 1] = l0;
            Ml[(r0 + 8) * 4 + 0] = m1; Ml[(r0 + 8) * 4 + 1] = l1;
        }
    }
    __syncthreads();
    if (wn == 1) {
        const int b = bh >> 3, h = bh & 7;
        const float mo0 = Ml[r0 * 4 + 0], lo0 = Ml[r0 * 4 + 1];
        const float mo1 = Ml[(r0 + 8) * 4 + 0], lo1 = Ml[(r0 + 8) * 4 + 1];
        const float mg0 = fmaxf(mo0, m0), mg1 = fmaxf(mo1, m1);
        const float so0 = ex2(mo0 - mg0), sw0 = ex2(m0 - mg0);
        const float so1 = ex2(mo1 - mg1), sw1 = ex2(m1 - mg1);
        const float inv0 = 1.f / (lo0 * so0 + l0 * sw0);
        const float inv1 = 1.f / (lo1 * so1 + l1 * sw1);
        const int n0 = q0 + r0, n1 = n0 + 8;
        #pragma unroll
        for (int nt = 0; nt < 4; nt++) {
            const int c = nt * 8 + tig * 2;
            if (n0 < NQ) {
                const size_t base = ((size_t)n0 * BATCH + b) * CDIM + h * DV + c;
                g_Oattn[base]     = (Os[r0 * 36 + c]     * so0 + oacc[nt][0] * sw0) * inv0;
                g_Oattn[base + 1] = (Os[r0 * 36 + c + 1] * so0 + oacc[nt][1] * sw0) * inv0;
            }
            if (n1 < NQ) {
                const size_t base = ((size_t)n1 * BATCH + b) * CDIM + h * DV + c;
                g_Oattn[base]     = (Os[(r0 + 8) * 36 + c]     * so1 + oacc[nt][2] * sw1) * inv1;
                g_Oattn[base + 1] = (Os[(r0 + 8) * 36 + c + 1] * so1 + oacc[nt][3] * sw1) * inv1;
            }
        }
    }
}

// ---------------------------------------------------------------------------
extern "C" void kernel_launch(void* const* d_in, const int* in_sizes, int n_in,
                              void* d_out, int out_size)
{
    const float* query    = (const float*)d_in[0];
    const float* key      = (const float*)d_in[1];
    const float* value    = (const float*)d_in[2];
    const float* querypos = (const float*)d_in[3];
    const float* keypos   = (const float*)d_in[4];
    const float* qsine    = (const float*)d_in[5];
    const float* Wqc = (const float*)d_in[6];  const float* bqc = (const float*)d_in[7];
    const float* Wqp = (const float*)d_in[8];  const float* bqp = (const float*)d_in[9];
    const float* Wqs = (const float*)d_in[10]; const float* bqs = (const float*)d_in[11];
    const float* Wkc = (const float*)d_in[12]; const float* bkc = (const float*)d_in[13];
    const float* Wkp = (const float*)d_in[14]; const float* bkp = (const float*)d_in[15];
    const float* Wv  = (const float*)d_in[16]; const float* bv  = (const float*)d_in[17];
    const float* Wo  = (const float*)d_in[18]; const float* bo  = (const float*)d_in[19];
    float* out = (float*)d_out;

    static bool attr_done = false;
    if (!attr_done) {
        cudaFuncSetAttribute(proj_fused, cudaFuncAttributeMaxDynamicSharedMemorySize, PROJ_SMEM);
        cudaFuncSetAttribute(proj_out,   cudaFuncAttributeMaxDynamicSharedMemorySize, PROJ_SMEM);
        cudaFuncSetAttribute(attn_mma,   cudaFuncAttributeMaxDynamicSharedMemorySize, ATT_SMEM_BYTES);
        attr_done = true;
    }

    proj_fused<<<1140, 256, PROJ_SMEM>>>(key, keypos, value, query, querypos, qsine,
                                         Wkc, Wkp, Wv, Wqc, Wqp, Wqs,
                                         bkc, bkp, bv, bqc, bqp, bqs);
    attn_mma<<<dim3((NQ + 63) / 64, 32), 256, ATT_SMEM_BYTES>>>();
    proj_out<<<dim3(29, 4), 256, PROJ_SMEM>>>(Wo, bo, query, out);
}

// round 8
// speedup vs baseline: 5.5061x; 1.0502x over previous
#include <cuda_runtime.h>
#include <cuda_bf16.h>
#include <cstdint>
#include <cstddef>

// ---------------------------------------------------------------------------
// Conditional-DETR cross attention — bf16 projections + bf16 flash attention.
// Final out-projection stays TF32 (accuracy guard on the un-attenuated path).
// ---------------------------------------------------------------------------

#define NQ    900
#define NK    4096
#define BATCH 4
#define CDIM  256
#define NH    8
#define DV    32
#define DQK   64
// 0.125 * log2(e): softmax in exp2 domain
#define QSCALE_L2E 0.1803368801111204f

__device__ __nv_bfloat16 g_Kcat[(size_t)32 * NK * DQK];
__device__ __nv_bfloat16 g_Vh[(size_t)32 * DV * NK];
__device__ __nv_bfloat16 g_Qcat[(size_t)32 * NQ * DQK];
__device__ float         g_Oattn[(size_t)NQ * BATCH * CDIM]; // [n][b][h*32+v]
__device__ __nv_bfloat16 g_Wb[(size_t)6 * 65536];            // bf16 permuted weights

#define M_KPC  0
#define M_V    1
#define M_QALL 2
#define M_OUT  3

__device__ __forceinline__ uint32_t f2tf(float f) {
    uint32_t u; asm("cvt.rna.tf32.f32 %0, %1;" : "=r"(u) : "f"(f)); return u;
}
__device__ __forceinline__ uint32_t packbf(float lo, float hi) {
    uint32_t r; asm("cvt.rn.bf16x2.f32 %0, %1, %2;" : "=r"(r) : "f"(hi), "f"(lo));
    return r;
}
__device__ __forceinline__ float ex2(float x) {
    float r; asm("ex2.approx.ftz.f32 %0, %1;" : "=f"(r) : "f"(x)); return r;
}

__device__ __forceinline__ void mma8(float* d, const uint32_t* a, const uint32_t* b) {
    asm volatile(
        "mma.sync.aligned.m16n8k8.row.col.f32.tf32.tf32.f32 "
        "{%0,%1,%2,%3}, {%4,%5,%6,%7}, {%8,%9}, {%0,%1,%2,%3};"
        : "+f"(d[0]), "+f"(d[1]), "+f"(d[2]), "+f"(d[3])
        : "r"(a[0]), "r"(a[1]), "r"(a[2]), "r"(a[3]), "r"(b[0]), "r"(b[1]));
}
__device__ __forceinline__ void mma16(float* d, const uint32_t* a, const uint32_t* b) {
    asm volatile(
        "mma.sync.aligned.m16n8k16.row.col.f32.bf16.bf16.f32 "
        "{%0,%1,%2,%3}, {%4,%5,%6,%7}, {%8,%9}, {%0,%1,%2,%3};"
        : "+f"(d[0]), "+f"(d[1]), "+f"(d[2]), "+f"(d[3])
        : "r"(a[0]), "r"(a[1]), "r"(a[2]), "r"(a[3]), "r"(b[0]), "r"(b[1]));
}

__device__ __forceinline__ void cpa16(uint32_t dst, const void* src, int sz) {
    asm volatile("cp.async.cg.shared.global [%0], [%1], 16, %2;"
                 :: "r"(dst), "l"(src), "r"(sz));
}
#define CP_COMMIT asm volatile("cp.async.commit_group;" ::: "memory")
#define CP_WAIT0  asm volatile("cp.async.wait_group 0;" ::: "memory")

// fragment permutation within each 32-element block (bf16x2-pair granular)
__device__ __forceinline__ int pmap(int x) {
    const int pos = x & 15, gg = (x >> 4) & 1;
    return (x & ~31) | (((pos & 7) >> 1) << 3) | (gg << 2) | ((pos >> 3) << 1) | (pos & 1);
}
// uint32 (bf16-pair) slot for pair index p (0..15) within a 32-elem block
__device__ __forceinline__ int u32slot(int p) {
    return ((p & 3) << 2) | ((p >> 3) << 1) | ((p >> 2) & 1);
}

// ---------------------------------------------------------------------------
// weight convert: 6 × [256][256] float -> bf16 permuted. 384 blocks × 256 thr.
// ---------------------------------------------------------------------------
__global__ __launch_bounds__(256)
void wconv(const float* __restrict__ Wkc, const float* __restrict__ Wkp,
           const float* __restrict__ Wv,  const float* __restrict__ Wqc,
           const float* __restrict__ Wqp, const float* __restrict__ Wqs)
{
    const float* srcs[6] = {Wkc, Wkp, Wv, Wqc, Wqp, Wqs};
    const int idx = blockIdx.x * 256 + threadIdx.x;   // 0..98303
    const int w = idx >> 14;
    const int rem = idx & 16383;
    const int c = rem >> 6;
    const int s = (rem & 63) * 4;
    float4 v = *(const float4*)&srcs[w][c * 256 + s];
    uint32_t* dst = (uint32_t*)&g_Wb[(size_t)w * 65536 + c * 256 + (s & ~31)];
    const int p0 = (s & 31) >> 1;
    dst[u32slot(p0)]     = packbf(v.x, v.y);
    dst[u32slot(p0 + 1)] = packbf(v.z, v.w);
}

// ---------------------------------------------------------------------------
// bf16 projection GEMM. Tile 128x64, BK=32, 8 warps (4x2), 1 sync/chunk.
// A: LDG float4 -> cvt -> permuted STS (reg double buffer).
// B: cp.async of pre-permuted bf16 weights.
// ---------------------------------------------------------------------------
#define PROJB_SMEM (2 * (128 * 32 + 64 * 32) * 2)   // 24576 B

template<int MODE>
__device__ __forceinline__ void projb_body(
    int bx, int by,
    const float* __restrict__ A0, const float* __restrict__ A1,
    const float* __restrict__ A2,
    const __nv_bfloat16* __restrict__ W0, const __nv_bfloat16* __restrict__ W1,
    const __nv_bfloat16* __restrict__ W2,
    const float* __restrict__ b0a, const float* __restrict__ b0b,
    const float* __restrict__ b1, int M)
{
    extern __shared__ __nv_bfloat16 bsm[];
    __nv_bfloat16* As = bsm;                  // [2][128][32]
    __nv_bfloat16* Ws = bsm + 2 * 128 * 32;   // [2][64][32]
    const uint32_t wsB = (uint32_t)__cvta_generic_to_shared(Ws);

    const int tid = threadIdx.x;
    const int lane = tid & 31;
    const int g = lane >> 2, tig = lane & 3;
    const int wm = (tid >> 5) >> 1, wn = (tid >> 5) & 1;
    const int m0 = bx * 128;
    const int c0 = by * 64;

    // hoisted A-load/store indices (loop invariant)
    int r_a[4], sl0[4], sl1[4];
    #pragma unroll
    for (int t = 0; t < 4; t++) {
        int i = tid + t * 256;
        r_a[t] = i >> 3;
        int j = i & 7;                  // float4 index within row
        sl0[t] = u32slot(2 * j);
        sl1[t] = u32slot(2 * j + 1);
    }
    const int rb = tid >> 2;            // B row for cp.async
    const int sb = (tid & 3) * 8;       // bf16 offset

    float4 abuf[4];
    float acc0[2][4][4] = {};
    float acc1[2][4][4] = {};
    const int nchunk = (MODE == M_KPC) ? 16 : (MODE == M_QALL) ? 24 : 8;

    auto pick = [&](int kc, const float*& Ap, const __nv_bfloat16*& Wp, int& k0) {
        if (MODE == M_KPC) {
            if (kc < 8) { Ap = A0; Wp = W0; k0 = kc * 32; }
            else        { Ap = A1; Wp = W1; k0 = (kc - 8) * 32; }
        } else if (MODE == M_QALL) {
            if (kc < 8)       { Ap = A0; Wp = W0; k0 = kc * 32; }
            else if (kc < 16) { Ap = A1; Wp = W1; k0 = (kc - 8) * 32; }
            else              { Ap = A2; Wp = W2; k0 = (kc - 16) * 32; }
        } else { Ap = A0; Wp = W0; k0 = kc * 32; }
    };

    auto ldgA = [&](int kc) {
        const float* Ap; const __nv_bfloat16* Wp; int k0;
        pick(kc, Ap, Wp, k0);
        #pragma unroll
        for (int t = 0; t < 4; t++) {
            int row = m0 + r_a[t];
            int s = ((tid + t * 256) & 7) * 4;
            abuf[t] = (row < M) ? *(const float4*)&Ap[(size_t)row * CDIM + k0 + s]
                                : make_float4(0.f, 0.f, 0.f, 0.f);
        }
    };
    auto cpaB = [&](int kc, int buf) {
        const float* Ap; const __nv_bfloat16* Wp; int k0;
        pick(kc, Ap, Wp, k0);
        cpa16(wsB + (((buf * 64 + rb) * 32 + sb) << 1),
              Wp + (size_t)(c0 + rb) * CDIM + k0 + sb, 16);
    };
    auto stsA = [&](int buf) {
        #pragma unroll
        for (int t = 0; t < 4; t++) {
            uint32_t* dst = (uint32_t*)(As + (buf * 128 + r_a[t]) * 32);
            dst[sl0[t]] = packbf(abuf[t].x, abuf[t].y);
            dst[sl1[t]] = packbf(abuf[t].z, abuf[t].w);
        }
    };
    auto compute = [&](int buf, float (&acc)[2][4][4]) {
        const __nv_bfloat16* Ab = As + buf * 128 * 32;
        const __nv_bfloat16* Wb = Ws + buf * 64 * 32;
        uint4 ua[2][2];
        #pragma unroll
        for (int mt = 0; mt < 2; mt++) {
            int r = wm * 32 + mt * 16 + g;
            ua[mt][0] = *(const uint4*)(Ab + r * 32 + tig * 8);
            ua[mt][1] = *(const uint4*)(Ab + (r + 8) * 32 + tig * 8);
        }
        uint4 ub[4];
        #pragma unroll
        for (int nt = 0; nt < 4; nt++)
            ub[nt] = *(const uint4*)(Wb + (wn * 32 + nt * 8 + g) * 32 + tig * 8);
        #pragma unroll
        for (int mt = 0; mt < 2; mt++) {
            uint32_t a0[4] = {ua[mt][0].x, ua[mt][1].x, ua[mt][0].y, ua[mt][1].y};
            uint32_t a1[4] = {ua[mt][0].z, ua[mt][1].z, ua[mt][0].w, ua[mt][1].w};
            #pragma unroll
            for (int nt = 0; nt < 4; nt++) {
                uint32_t b0[2] = {ub[nt].x, ub[nt].y};
                uint32_t b1v[2] = {ub[nt].z, ub[nt].w};
                mma16(acc[mt][nt], a0, b0);
                mma16(acc[mt][nt], a1, b1v);
            }
        }
    };

    ldgA(0);
    cpaB(0, 0);
    CP_COMMIT;
    stsA(0);
    CP_WAIT0;
    __syncthreads();
    for (int kc = 0; kc < nchunk; kc++) {
        if (kc + 1 < nchunk) { ldgA(kc + 1); cpaB(kc + 1, (kc + 1) & 1); CP_COMMIT; }
        const bool sec = (MODE == M_KPC && kc >= 8) || (MODE == M_QALL && kc >= 16);
        if (sec) compute(kc & 1, acc1);
        else     compute(kc & 1, acc0);
        if (kc + 1 < nchunk) { stsA((kc + 1) & 1); CP_WAIT0; __syncthreads(); }
    }

    #pragma unroll
    for (int mt = 0; mt < 2; mt++)
    #pragma unroll
    for (int nt = 0; nt < 4; nt++)
    #pragma unroll
    for (int cr = 0; cr < 4; cr++) {
        const int row = m0 + wm * 32 + mt * 16 + g + ((cr >= 2) ? 8 : 0);
        if (row >= M) continue;
        const int col = c0 + wn * 32 + nt * 8 + tig * 2 + (cr & 1);

        if (MODE == M_KPC) {
            const int m = row >> 2, b = row & 3, h = col >> 5, ii = col & 31;
            const float vkp = acc1[mt][nt][cr] + b1[col];
            const float vk  = acc0[mt][nt][cr] + b0a[col] + vkp;
            const size_t base = ((size_t)(b * NH + h) * NK + m) * DQK;
            g_Kcat[base + pmap(ii)]      = __float2bfloat16(vk);
            g_Kcat[base + pmap(ii + 32)] = __float2bfloat16(vkp);
        } else if (MODE == M_V) {
            const int m = row >> 2, b = row & 3, h = col >> 5, ii = col & 31;
            g_Vh[((size_t)(b * NH + h) * DV + ii) * NK + (m & ~31) + pmap(m & 31)] =
                __float2bfloat16(acc0[mt][nt][cr] + b0a[col]);
        } else if (MODE == M_QALL) {
            const int n = row >> 2, b = row & 3, h = col >> 5, ii = col & 31;
            const size_t base = ((size_t)(b * NH + h) * NQ + n) * DQK;
            g_Qcat[base + pmap(ii)] =
                __float2bfloat16((acc0[mt][nt][cr] + b0a[col] + b0b[col]) * QSCALE_L2E);
            g_Qcat[base + pmap(ii + 32)] =
                __float2bfloat16((acc1[mt][nt][cr] + b1[col]) * QSCALE_L2E);
        }
    }
}

// fused: KPC (512 blocks) | V (512) | QALL (116)
__global__ __launch_bounds__(256, 2)
void proj_fused(const float* __restrict__ key, const float* __restrict__ keypos,
                const float* __restrict__ value,
                const float* __restrict__ query, const float* __restrict__ querypos,
                const float* __restrict__ qsine,
                const float* __restrict__ bkc, const float* __restrict__ bkp,
                const float* __restrict__ bv,
                const float* __restrict__ bqc, const float* __restrict__ bqp,
                const float* __restrict__ bqs)
{
    const __nv_bfloat16* Wkc = g_Wb;
    const __nv_bfloat16* Wkp = g_Wb + 1 * 65536;
    const __nv_bfloat16* Wv  = g_Wb + 2 * 65536;
    const __nv_bfloat16* Wqc = g_Wb + 3 * 65536;
    const __nv_bfloat16* Wqp = g_Wb + 4 * 65536;
    const __nv_bfloat16* Wqs = g_Wb + 5 * 65536;

    int id = blockIdx.x;
    if (id < 512) {
        projb_body<M_KPC>(id & 127, id >> 7, key, keypos, nullptr,
                          Wkc, Wkp, nullptr, bkc, nullptr, bkp, NK * BATCH);
    } else if (id < 1024) {
        id -= 512;
        projb_body<M_V>(id & 127, id >> 7, value, nullptr, nullptr,
                        Wv, nullptr, nullptr, bv, nullptr, nullptr, NK * BATCH);
    } else {
        id -= 1024;
        projb_body<M_QALL>(id % 29, id / 29, query, querypos, qsine,
                           Wqc, Wqp, Wqs, bqc, bqp, bqs, NQ * BATCH);
    }
}

// ---------------------------------------------------------------------------
// TF32 out-projection (unchanged accuracy-critical path): tile 128x64, BK=32.
// ---------------------------------------------------------------------------
#define PROJ_SMEM ((2*128*36 + 2*64*36) * 4)

__global__ __launch_bounds__(256)
void proj_out(const float* __restrict__ Wo, const float* __restrict__ bo,
              const float* __restrict__ addsrc, float* __restrict__ outp)
{
    extern __shared__ float psm[];
    float* As = psm;
    float* Ws = psm + 2 * 128 * 36;
    const uint32_t asB = (uint32_t)__cvta_generic_to_shared(As);
    const uint32_t wsB = (uint32_t)__cvta_generic_to_shared(Ws);

    const int tid = threadIdx.x;
    const int lane = tid & 31;
    const int g = lane >> 2, tig = lane & 3;
    const int wm = (tid >> 5) >> 1, wn = (tid >> 5) & 1;
    const int m0 = blockIdx.x * 128;
    const int c0 = blockIdx.y * 64;
    const int M = NQ * BATCH;

    float acc[2][4][4] = {};

    auto load_chunk = [&](int kc, int buf) {
        const int k0 = kc * 32;
        #pragma unroll
        for (int t = 0; t < 4; t++) {
            int i = tid + t * 256;
            int r = i >> 3, s = (i & 7) * 4;
            int row = m0 + r;
            uint32_t dst = asB + (((buf * 128 + r) * 36 + s) << 2);
            cpa16(dst, g_Oattn + (size_t)row * CDIM + k0 + s, row < M ? 16 : 0);
        }
        #pragma unroll
        for (int t = 0; t < 2; t++) {
            int i = tid + t * 256;
            int r = i >> 3, s = (i & 7) * 4;
            uint32_t dst = wsB + (((buf * 64 + r) * 36 + s) << 2);
            cpa16(dst, Wo + (size_t)(c0 + r) * CDIM + k0 + s, 16);
        }
    };
    auto compute = [&](int buf) {
        const float* Ab = As + buf * 128 * 36;
        const float* Wb = Ws + buf * 64 * 36;
        #pragma unroll
        for (int ks = 0; ks < 4; ks++) {
            uint32_t a[2][4], b[4][2];
            #pragma unroll
            for (int mt = 0; mt < 2; mt++) {
                int r = wm * 32 + mt * 16 + g;
                a[mt][0] = f2tf(Ab[r * 36 + ks * 8 + tig]);
                a[mt][1] = f2tf(Ab[(r + 8) * 36 + ks * 8 + tig]);
                a[mt][2] = f2tf(Ab[r * 36 + ks * 8 + tig + 4]);
                a[mt][3] = f2tf(Ab[(r + 8) * 36 + ks * 8 + tig + 4]);
            }
            #pragma unroll
            for (int nt = 0; nt < 4; nt++) {
                int c = wn * 32 + nt * 8 + g;
                b[nt][0] = f2tf(Wb[c * 36 + ks * 8 + tig]);
                b[nt][1] = f2tf(Wb[c * 36 + ks * 8 + tig + 4]);
            }
            #pragma unroll
            for (int mt = 0; mt < 2; mt++)
                #pragma unroll
                for (int nt = 0; nt < 4; nt++)
                    mma8(acc[mt][nt], a[mt], b[nt]);
        }
    };

    load_chunk(0, 0);
    CP_COMMIT; CP_WAIT0;
    __syncthreads();
    for (int kc = 0; kc < 8; kc++) {
        if (kc + 1 < 8) { load_chunk(kc + 1, (kc + 1) & 1); CP_COMMIT; }
        compute(kc & 1);
        if (kc + 1 < 8) { CP_WAIT0; __syncthreads(); }
    }

    #pragma unroll
    for (int mt = 0; mt < 2; mt++)
    #pragma unroll
    for (int nt = 0; nt < 4; nt++)
    #pragma unroll
    for (int cr = 0; cr < 4; cr++) {
        const int row = m0 + wm * 32 + mt * 16 + g + ((cr >= 2) ? 8 : 0);
        if (row >= M) continue;
        const int col = c0 + wn * 32 + nt * 8 + tig * 2 + (cr & 1);
        outp[(size_t)row * CDIM + col] =
            addsrc[(size_t)row * CDIM + col] + acc[mt][nt][cr] + bo[col];
    }
}

// ---------------------------------------------------------------------------
// bf16 flash attention (unchanged from round 7).
// ---------------------------------------------------------------------------
#define ATT_Q_OFF   0
#define ATT_K_OFF   (64 * 96)
#define ATT_V_OFF   (ATT_K_OFF + 2 * 64 * 96)
#define ATT_SMEM_BYTES ((ATT_V_OFF + 2 * 32 * 96) * 2)     // 48 KB

__global__ __launch_bounds__(256, 2)
void attn_mma()
{
    extern __shared__ __nv_bfloat16 smb[];
    __nv_bfloat16* Qs = smb + ATT_Q_OFF;
    __nv_bfloat16* Ks = smb + ATT_K_OFF;
    __nv_bfloat16* Vs = smb + ATT_V_OFF;
    float* Os = (float*)Ks;
    float* Ml = (float*)Vs;
    const uint32_t qsB = (uint32_t)__cvta_generic_to_shared(Qs);
    const uint32_t ksB = (uint32_t)__cvta_generic_to_shared(Ks);
    const uint32_t vsB = (uint32_t)__cvta_generic_to_shared(Vs);

    const int tid = threadIdx.x;
    const int w = tid >> 5, lane = tid & 31;
    const int g = lane >> 2, tig = lane & 3;
    const int wm = w >> 1, wn = w & 1;
    const int bh = blockIdx.y;
    const int q0 = blockIdx.x * 64;

    auto issueQ = [&]() {
        #pragma unroll
        for (int t = 0; t < 2; t++) {
            int i = tid + t * 256;
            int r = i >> 3, c8 = i & 7;
            int n = q0 + r;
            uint32_t dst = qsB + (r * 96 + c8 * 8) * 2;
            cpa16(dst, &g_Qcat[((size_t)bh * NQ + (n < NQ ? n : 0)) * DQK + c8 * 8],
                  n < NQ ? 16 : 0);
        }
    };
    auto issueKV = [&](int kt, int buf) {
        const int mbase = kt * 64;
        #pragma unroll
        for (int t = 0; t < 2; t++) {
            int i = tid + t * 256;
            int r = i >> 3, c8 = i & 7;
            uint32_t dst = ksB + ((buf * 64 + r) * 96 + c8 * 8) * 2;
            cpa16(dst, &g_Kcat[((size_t)bh * NK + mbase + r) * DQK + c8 * 8], 16);
        }
        {
            int r = tid >> 3, c8 = tid & 7;
            uint32_t dst = vsB + ((buf * 32 + r) * 96 + c8 * 8) * 2;
            cpa16(dst, &g_Vh[((size_t)bh * DV + r) * NK + mbase + c8 * 8], 16);
        }
    };

    issueQ();
    issueKV(0, 0);
    CP_COMMIT;

    const __nv_bfloat16* kbase = Ks + (wn * 32 + g) * 96 + tig * 8;
    const __nv_bfloat16* vbase = Vs + g * 96 + wn * 32 + tig * 8;

    uint32_t qa[4][4];
    float oacc[4][4] = {};
    float m0 = -1e30f, m1 = -1e30f, l0 = 0.f, l1 = 0.f;

    CP_WAIT0;
    __syncthreads();

    {
        const int r = wm * 16 + g;
        #pragma unroll
        for (int p = 0; p < 2; p++) {
            uint4 ug  = *(const uint4*)(Qs + r * 96 + p * 32 + tig * 8);
            uint4 ug8 = *(const uint4*)(Qs + (r + 8) * 96 + p * 32 + tig * 8);
            qa[2*p][0]   = ug.x; qa[2*p][1]   = ug8.x;
            qa[2*p][2]   = ug.y; qa[2*p][3]   = ug8.y;
            qa[2*p+1][0] = ug.z; qa[2*p+1][1] = ug8.z;
            qa[2*p+1][2] = ug.w; qa[2*p+1][3] = ug8.w;
        }
    }

    const int NT = NK / 64;
    for (int kt = 0; kt < NT; kt++) {
        const int buf = kt & 1;
        if (kt + 1 < NT) { issueKV(kt + 1, buf ^ 1); CP_COMMIT; }

        const __nv_bfloat16* Kb = kbase + buf * (64 * 96);
        const __nv_bfloat16* Vb = vbase + buf * (32 * 96);

        float s[4][4];
        #pragma unroll
        for (int nt = 0; nt < 4; nt++) {
            uint4 kq0 = *(const uint4*)(Kb + nt * (8 * 96));
            uint4 kq1 = *(const uint4*)(Kb + nt * (8 * 96) + 32);
            s[nt][0] = s[nt][1] = s[nt][2] = s[nt][3] = 0.f;
            { uint32_t b[2] = {kq0.x, kq0.y}; mma16(s[nt], qa[0], b); }
            { uint32_t b[2] = {kq0.z, kq0.w}; mma16(s[nt], qa[1], b); }
            { uint32_t b[2] = {kq1.x, kq1.y}; mma16(s[nt], qa[2], b); }
            { uint32_t b[2] = {kq1.z, kq1.w}; mma16(s[nt], qa[3], b); }
        }

        float pm0 = -1e30f, pm1 = -1e30f;
        #pragma unroll
        for (int nt = 0; nt < 4; nt++) {
            pm0 = fmaxf(pm0, fmaxf(s[nt][0], s[nt][1]));
            pm1 = fmaxf(pm1, fmaxf(s[nt][2], s[nt][3]));
        }
        pm0 = fmaxf(pm0, __shfl_xor_sync(~0u, pm0, 1));
        pm0 = fmaxf(pm0, __shfl_xor_sync(~0u, pm0, 2));
        pm1 = fmaxf(pm1, __shfl_xor_sync(~0u, pm1, 1));
        pm1 = fmaxf(pm1, __shfl_xor_sync(~0u, pm1, 2));
        const float mn0 = fmaxf(m0, pm0), mn1 = fmaxf(m1, pm1);
        const float al0 = ex2(m0 - mn0), al1 = ex2(m1 - mn1);
        m0 = mn0; m1 = mn1;
        float ps0 = 0.f, ps1 = 0.f;
        #pragma unroll
        for (int nt = 0; nt < 4; nt++) {
            s[nt][0] = ex2(s[nt][0] - mn0);
            s[nt][1] = ex2(s[nt][1] - mn0);
            s[nt][2] = ex2(s[nt][2] - mn1);
            s[nt][3] = ex2(s[nt][3] - mn1);
            ps0 += s[nt][0] + s[nt][1];
            ps1 += s[nt][2] + s[nt][3];
        }
        ps0 += __shfl_xor_sync(~0u, ps0, 1); ps0 += __shfl_xor_sync(~0u, ps0, 2);
        ps1 += __shfl_xor_sync(~0u, ps1, 1); ps1 += __shfl_xor_sync(~0u, ps1, 2);
        l0 = l0 * al0 + ps0;
        l1 = l1 * al1 + ps1;
        #pragma unroll
        for (int nt = 0; nt < 4; nt++) {
            oacc[nt][0] *= al0; oacc[nt][1] *= al0;
            oacc[nt][2] *= al1; oacc[nt][3] *= al1;
        }

        uint4 vq[4];
        #pragma unroll
        for (int nt = 0; nt < 4; nt++)
            vq[nt] = *(const uint4*)(Vb + nt * (8 * 96));
        #pragma unroll
        for (int c = 0; c < 2; c++) {
            uint32_t a[4];
            a[0] = packbf(s[2*c][0],   s[2*c][1]);
            a[1] = packbf(s[2*c][2],   s[2*c][3]);
            a[2] = packbf(s[2*c+1][0], s[2*c+1][1]);
            a[3] = packbf(s[2*c+1][2], s[2*c+1][3]);
            #pragma unroll
            for (int nt = 0; nt < 4; nt++) {
                uint32_t b[2] = { c ? vq[nt].z : vq[nt].x,
                                  c ? vq[nt].w : vq[nt].y };
                mma16(oacc[nt], a, b);
            }
        }

        if (kt + 1 < NT) { CP_WAIT0; __syncthreads(); }
    }

    __syncthreads();

    const int r0 = wm * 16 + g;
    if (wn == 0) {
        #pragma unroll
        for (int nt = 0; nt < 4; nt++) {
            const int c = nt * 8 + tig * 2;
            Os[r0 * 36 + c]           = oacc[nt][0];
            Os[r0 * 36 + c + 1]       = oacc[nt][1];
            Os[(r0 + 8) * 36 + c]     = oacc[nt][2];
            Os[(r0 + 8) * 36 + c + 1] = oacc[nt][3];
        }
        if (tig == 0) {
            Ml[r0 * 4 + 0] = m0; Ml[r0 * 4 + 1] = l0;
            Ml[(r0 + 8) * 4 + 0] = m1; Ml[(r0 + 8) * 4 + 1] = l1;
        }
    }
    __syncthreads();
    if (wn == 1) {
        const int b = bh >> 3, h = bh & 7;
        const float mo0 = Ml[r0 * 4 + 0], lo0 = Ml[r0 * 4 + 1];
        const float mo1 = Ml[(r0 + 8) * 4 + 0], lo1 = Ml[(r0 + 8) * 4 + 1];
        const float mg0 = fmaxf(mo0, m0), mg1 = fmaxf(mo1, m1);
        const float so0 = ex2(mo0 - mg0), sw0 = ex2(m0 - mg0);
        const float so1 = ex2(mo1 - mg1), sw1 = ex2(m1 - mg1);
        const float inv0 = 1.f / (lo0 * so0 + l0 * sw0);
        const float inv1 = 1.f / (lo1 * so1 + l1 * sw1);
        const int n0 = q0 + r0, n1 = n0 + 8;
        #pragma unroll
        for (int nt = 0; nt < 4; nt++) {
            const int c = nt * 8 + tig * 2;
            if (n0 < NQ) {
                const size_t base = ((size_t)n0 * BATCH + b) * CDIM + h * DV + c;
                g_Oattn[base]     = (Os[r0 * 36 + c]     * so0 + oacc[nt][0] * sw0) * inv0;
                g_Oattn[base + 1] = (Os[r0 * 36 + c + 1] * so0 + oacc[nt][1] * sw0) * inv0;
            }
            if (n1 < NQ) {
                const size_t base = ((size_t)n1 * BATCH + b) * CDIM + h * DV + c;
                g_Oattn[base]     = (Os[(r0 + 8) * 36 + c]     * so1 + oacc[nt][2] * sw1) * inv1;
                g_Oattn[base + 1] = (Os[(r0 + 8) * 36 + c + 1] * so1 + oacc[nt][3] * sw1) * inv1;
            }
        }
    }
}

// ---------------------------------------------------------------------------
extern "C" void kernel_launch(void* const* d_in, const int* in_sizes, int n_in,
                              void* d_out, int out_size)
{
    const float* query    = (const float*)d_in[0];
    const float* key      = (const float*)d_in[1];
    const float* value    = (const float*)d_in[2];
    const float* querypos = (const float*)d_in[3];
    const float* keypos   = (const float*)d_in[4];
    const float* qsine    = (const float*)d_in[5];
    const float* Wqc = (const float*)d_in[6];  const float* bqc = (const float*)d_in[7];
    const float* Wqp = (const float*)d_in[8];  const float* bqp = (const float*)d_in[9];
    const float* Wqs = (const float*)d_in[10]; const float* bqs = (const float*)d_in[11];
    const float* Wkc = (const float*)d_in[12]; const float* bkc = (const float*)d_in[13];
    const float* Wkp = (const float*)d_in[14]; const float* bkp = (const float*)d_in[15];
    const float* Wv  = (const float*)d_in[16]; const float* bv  = (const float*)d_in[17];
    const float* Wo  = (const float*)d_in[18]; const float* bo  = (const float*)d_in[19];
    float* out = (float*)d_out;

    static bool attr_done = false;
    if (!attr_done) {
        cudaFuncSetAttribute(proj_out, cudaFuncAttributeMaxDynamicSharedMemorySize, PROJ_SMEM);
        cudaFuncSetAttribute(attn_mma, cudaFuncAttributeMaxDynamicSharedMemorySize, ATT_SMEM_BYTES);
        attr_done = true;
    }

    wconv<<<384, 256>>>(Wkc, Wkp, Wv, Wqc, Wqp, Wqs);
    proj_fused<<<1140, 256, PROJB_SMEM>>>(key, keypos, value, query, querypos, qsine,
                                          bkc, bkp, bv, bqc, bqp, bqs);
    attn_mma<<<dim3((NQ + 63) / 64, 32), 256, ATT_SMEM_BYTES>>>();
    proj_out<<<dim3(29, 4), 256, PROJ_SMEM>>>(Wo, bo, query, out);
}

// round 9
// speedup vs baseline: 5.9494x; 1.0805x over previous
#include <cuda_runtime.h>
#include <cuda_bf16.h>
#include <cstdint>
#include <cstddef>

// ---------------------------------------------------------------------------
// Conditional-DETR cross attention — bf16 projections + bf16 flash attention.
// Final out-projection stays TF32 (accuracy guard on the un-attenuated path).
// ---------------------------------------------------------------------------

#define NQ    900
#define NK    4096
#define BATCH 4
#define CDIM  256
#define NH    8
#define DV    32
#define DQK   64
// 0.125 * log2(e): softmax in exp2 domain
#define QSCALE_L2E 0.1803368801111204f

__device__ __nv_bfloat16 g_Kcat[(size_t)32 * NK * DQK];
__device__ __nv_bfloat16 g_Vh[(size_t)32 * DV * NK];
__device__ __nv_bfloat16 g_Qcat[(size_t)32 * NQ * DQK];
__device__ float         g_Oattn[(size_t)NQ * BATCH * CDIM]; // [n][b][h*32+v]
__device__ __nv_bfloat16 g_Wb[(size_t)6 * 65536];            // bf16 permuted weights

#define M_KPC  0
#define M_V    1
#define M_QALL 2
#define M_OUT  3

__device__ __forceinline__ uint32_t f2tf(float f) {
    uint32_t u; asm("cvt.rna.tf32.f32 %0, %1;" : "=r"(u) : "f"(f)); return u;
}
__device__ __forceinline__ uint32_t packbf(float lo, float hi) {
    uint32_t r; asm("cvt.rn.bf16x2.f32 %0, %1, %2;" : "=r"(r) : "f"(hi), "f"(lo));
    return r;
}
__device__ __forceinline__ float ex2(float x) {
    float r; asm("ex2.approx.ftz.f32 %0, %1;" : "=f"(r) : "f"(x)); return r;
}

__device__ __forceinline__ void mma8(float* d, const uint32_t* a, const uint32_t* b) {
    asm volatile(
        "mma.sync.aligned.m16n8k8.row.col.f32.tf32.tf32.f32 "
        "{%0,%1,%2,%3}, {%4,%5,%6,%7}, {%8,%9}, {%0,%1,%2,%3};"
        : "+f"(d[0]), "+f"(d[1]), "+f"(d[2]), "+f"(d[3])
        : "r"(a[0]), "r"(a[1]), "r"(a[2]), "r"(a[3]), "r"(b[0]), "r"(b[1]));
}
__device__ __forceinline__ void mma16(float* d, const uint32_t* a, const uint32_t* b) {
    asm volatile(
        "mma.sync.aligned.m16n8k16.row.col.f32.bf16.bf16.f32 "
        "{%0,%1,%2,%3}, {%4,%5,%6,%7}, {%8,%9}, {%0,%1,%2,%3};"
        : "+f"(d[0]), "+f"(d[1]), "+f"(d[2]), "+f"(d[3])
        : "r"(a[0]), "r"(a[1]), "r"(a[2]), "r"(a[3]), "r"(b[0]), "r"(b[1]));
}

__device__ __forceinline__ void cpa16(uint32_t dst, const void* src, int sz) {
    asm volatile("cp.async.cg.shared.global [%0], [%1], 16, %2;"
                 :: "r"(dst), "l"(src), "r"(sz));
}
#define CP_COMMIT asm volatile("cp.async.commit_group;" ::: "memory")
#define CP_WAIT0  asm volatile("cp.async.wait_group 0;" ::: "memory")

// fragment permutation within each 32-element block (bf16x2-pair granular)
__device__ __forceinline__ int pmap(int x) {
    const int pos = x & 15, gg = (x >> 4) & 1;
    return (x & ~31) | (((pos & 7) >> 1) << 3) | (gg << 2) | ((pos >> 3) << 1) | (pos & 1);
}
// uint32 (bf16-pair) slot for pair index p (0..15) within a 32-elem block
__device__ __forceinline__ int u32slot(int p) {
    return ((p & 3) << 2) | ((p >> 3) << 1) | ((p >> 2) & 1);
}

// ---------------------------------------------------------------------------
// weight convert: 6 × [256][256] float -> bf16 permuted. 384 blocks × 256 thr.
// ---------------------------------------------------------------------------
__global__ __launch_bounds__(256)
void wconv(const float* __restrict__ Wkc, const float* __restrict__ Wkp,
           const float* __restrict__ Wv,  const float* __restrict__ Wqc,
           const float* __restrict__ Wqp, const float* __restrict__ Wqs)
{
    const float* srcs[6] = {Wkc, Wkp, Wv, Wqc, Wqp, Wqs};
    const int idx = blockIdx.x * 256 + threadIdx.x;   // 0..98303
    const int w = idx >> 14;
    const int rem = idx & 16383;
    const int c = rem >> 6;
    const int s = (rem & 63) * 4;
    float4 v = *(const float4*)&srcs[w][c * 256 + s];
    uint32_t* dst = (uint32_t*)&g_Wb[(size_t)w * 65536 + c * 256 + (s & ~31)];
    const int p0 = (s & 31) >> 1;
    dst[u32slot(p0)]     = packbf(v.x, v.y);
    dst[u32slot(p0 + 1)] = packbf(v.z, v.w);
}

// ---------------------------------------------------------------------------
// bf16 projection GEMM. Tile 128x64, BK=32, 8 warps (4x2), 1 sync/chunk.
// ---------------------------------------------------------------------------
#define PROJB_SMEM (2 * (128 * 32 + 64 * 32) * 2)   // 24576 B

template<int MODE>
__device__ __forceinline__ void projb_body(
    int bx, int by,
    const float* __restrict__ A0, const float* __restrict__ A1,
    const float* __restrict__ A2,
    const __nv_bfloat16* __restrict__ W0, const __nv_bfloat16* __restrict__ W1,
    const __nv_bfloat16* __restrict__ W2,
    const float* __restrict__ b0a, const float* __restrict__ b0b,
    const float* __restrict__ b1, int M)
{
    extern __shared__ __nv_bfloat16 bsm[];
    __nv_bfloat16* As = bsm;                  // [2][128][32]
    __nv_bfloat16* Ws = bsm + 2 * 128 * 32;   // [2][64][32]
    const uint32_t wsB = (uint32_t)__cvta_generic_to_shared(Ws);

    const int tid = threadIdx.x;
    const int lane = tid & 31;
    const int g = lane >> 2, tig = lane & 3;
    const int wm = (tid >> 5) >> 1, wn = (tid >> 5) & 1;
    const int m0 = bx * 128;
    const int c0 = by * 64;

    int r_a[4], sl0[4], sl1[4];
    #pragma unroll
    for (int t = 0; t < 4; t++) {
        int i = tid + t * 256;
        r_a[t] = i >> 3;
        int j = i & 7;
        sl0[t] = u32slot(2 * j);
        sl1[t] = u32slot(2 * j + 1);
    }
    const int rb = tid >> 2;
    const int sb = (tid & 3) * 8;

    float4 abuf[4];
    float acc0[2][4][4] = {};
    float acc1[2][4][4] = {};
    const int nchunk = (MODE == M_KPC) ? 16 : (MODE == M_QALL) ? 24 : 8;

    auto pick = [&](int kc, const float*& Ap, const __nv_bfloat16*& Wp, int& k0) {
        if (MODE == M_KPC) {
            if (kc < 8) { Ap = A0; Wp = W0; k0 = kc * 32; }
            else        { Ap = A1; Wp = W1; k0 = (kc - 8) * 32; }
        } else if (MODE == M_QALL) {
            if (kc < 8)       { Ap = A0; Wp = W0; k0 = kc * 32; }
            else if (kc < 16) { Ap = A1; Wp = W1; k0 = (kc - 8) * 32; }
            else              { Ap = A2; Wp = W2; k0 = (kc - 16) * 32; }
        } else { Ap = A0; Wp = W0; k0 = kc * 32; }
    };

    auto ldgA = [&](int kc) {
        const float* Ap; const __nv_bfloat16* Wp; int k0;
        pick(kc, Ap, Wp, k0);
        #pragma unroll
        for (int t = 0; t < 4; t++) {
            int row = m0 + r_a[t];
            int s = ((tid + t * 256) & 7) * 4;
            abuf[t] = (row < M) ? *(const float4*)&Ap[(size_t)row * CDIM + k0 + s]
                                : make_float4(0.f, 0.f, 0.f, 0.f);
        }
    };
    auto cpaB = [&](int kc, int buf) {
        const float* Ap; const __nv_bfloat16* Wp; int k0;
        pick(kc, Ap, Wp, k0);
        cpa16(wsB + (((buf * 64 + rb) * 32 + sb) << 1),
              Wp + (size_t)(c0 + rb) * CDIM + k0 + sb, 16);
    };
    auto stsA = [&](int buf) {
        #pragma unroll
        for (int t = 0; t < 4; t++) {
            uint32_t* dst = (uint32_t*)(As + (buf * 128 + r_a[t]) * 32);
            dst[sl0[t]] = packbf(abuf[t].x, abuf[t].y);
            dst[sl1[t]] = packbf(abuf[t].z, abuf[t].w);
        }
    };
    auto compute = [&](int buf, float (&acc)[2][4][4]) {
        const __nv_bfloat16* Ab = As + buf * 128 * 32;
        const __nv_bfloat16* Wb = Ws + buf * 64 * 32;
        uint4 ua[2][2];
        #pragma unroll
        for (int mt = 0; mt < 2; mt++) {
            int r = wm * 32 + mt * 16 + g;
            ua[mt][0] = *(const uint4*)(Ab + r * 32 + tig * 8);
            ua[mt][1] = *(const uint4*)(Ab + (r + 8) * 32 + tig * 8);
        }
        uint4 ub[4];
        #pragma unroll
        for (int nt = 0; nt < 4; nt++)
            ub[nt] = *(const uint4*)(Wb + (wn * 32 + nt * 8 + g) * 32 + tig * 8);
        #pragma unroll
        for (int mt = 0; mt < 2; mt++) {
            uint32_t a0[4] = {ua[mt][0].x, ua[mt][1].x, ua[mt][0].y, ua[mt][1].y};
            uint32_t a1[4] = {ua[mt][0].z, ua[mt][1].z, ua[mt][0].w, ua[mt][1].w};
            #pragma unroll
            for (int nt = 0; nt < 4; nt++) {
                uint32_t b0[2] = {ub[nt].x, ub[nt].y};
                uint32_t b1v[2] = {ub[nt].z, ub[nt].w};
                mma16(acc[mt][nt], a0, b0);
                mma16(acc[mt][nt], a1, b1v);
            }
        }
    };

    ldgA(0);
    cpaB(0, 0);
    CP_COMMIT;
    stsA(0);
    CP_WAIT0;
    __syncthreads();
    for (int kc = 0; kc < nchunk; kc++) {
        if (kc + 1 < nchunk) { ldgA(kc + 1); cpaB(kc + 1, (kc + 1) & 1); CP_COMMIT; }
        const bool sec = (MODE == M_KPC && kc >= 8) || (MODE == M_QALL && kc >= 16);
        if (sec) compute(kc & 1, acc1);
        else     compute(kc & 1, acc0);
        if (kc + 1 < nchunk) { stsA((kc + 1) & 1); CP_WAIT0; __syncthreads(); }
    }

    #pragma unroll
    for (int mt = 0; mt < 2; mt++)
    #pragma unroll
    for (int nt = 0; nt < 4; nt++)
    #pragma unroll
    for (int cr = 0; cr < 4; cr++) {
        const int row = m0 + wm * 32 + mt * 16 + g + ((cr >= 2) ? 8 : 0);
        if (row >= M) continue;
        const int col = c0 + wn * 32 + nt * 8 + tig * 2 + (cr & 1);

        if (MODE == M_KPC) {
            const int m = row >> 2, b = row & 3, h = col >> 5, ii = col & 31;
            const float vkp = acc1[mt][nt][cr] + b1[col];
            const float vk  = acc0[mt][nt][cr] + b0a[col] + vkp;
            const size_t base = ((size_t)(b * NH + h) * NK + m) * DQK;
            g_Kcat[base + pmap(ii)]      = __float2bfloat16(vk);
            g_Kcat[base + pmap(ii + 32)] = __float2bfloat16(vkp);
        } else if (MODE == M_V) {
            const int m = row >> 2, b = row & 3, h = col >> 5, ii = col & 31;
            g_Vh[((size_t)(b * NH + h) * DV + ii) * NK + (m & ~31) + pmap(m & 31)] =
                __float2bfloat16(acc0[mt][nt][cr] + b0a[col]);
        } else if (MODE == M_QALL) {
            const int n = row >> 2, b = row & 3, h = col >> 5, ii = col & 31;
            const size_t base = ((size_t)(b * NH + h) * NQ + n) * DQK;
            g_Qcat[base + pmap(ii)] =
                __float2bfloat16((acc0[mt][nt][cr] + b0a[col] + b0b[col]) * QSCALE_L2E);
            g_Qcat[base + pmap(ii + 32)] =
                __float2bfloat16((acc1[mt][nt][cr] + b1[col]) * QSCALE_L2E);
        }
    }
}

// fused, longest blocks FIRST: QALL (116, 24 chunks) | KPC (512, 16) | V (512, 8)
__global__ __launch_bounds__(256, 2)
void proj_fused(const float* __restrict__ key, const float* __restrict__ keypos,
                const float* __restrict__ value,
                const float* __restrict__ query, const float* __restrict__ querypos,
                const float* __restrict__ qsine,
                const float* __restrict__ bkc, const float* __restrict__ bkp,
                const float* __restrict__ bv,
                const float* __restrict__ bqc, const float* __restrict__ bqp,
                const float* __restrict__ bqs)
{
    const __nv_bfloat16* Wkc = g_Wb;
    const __nv_bfloat16* Wkp = g_Wb + 1 * 65536;
    const __nv_bfloat16* Wv  = g_Wb + 2 * 65536;
    const __nv_bfloat16* Wqc = g_Wb + 3 * 65536;
    const __nv_bfloat16* Wqp = g_Wb + 4 * 65536;
    const __nv_bfloat16* Wqs = g_Wb + 5 * 65536;

    int id = blockIdx.x;
    if (id < 116) {
        projb_body<M_QALL>(id % 29, id / 29, query, querypos, qsine,
                           Wqc, Wqp, Wqs, bqc, bqp, bqs, NQ * BATCH);
    } else if (id < 628) {
        id -= 116;
        projb_body<M_KPC>(id & 127, id >> 7, key, keypos, nullptr,
                          Wkc, Wkp, nullptr, bkc, nullptr, bkp, NK * BATCH);
    } else {
        id -= 628;
        projb_body<M_V>(id & 127, id >> 7, value, nullptr, nullptr,
                        Wv, nullptr, nullptr, bv, nullptr, nullptr, NK * BATCH);
    }
}

// ---------------------------------------------------------------------------
// TF32 out-projection: tile 128x64, BK=32.
// ---------------------------------------------------------------------------
#define PROJ_SMEM ((2*128*36 + 2*64*36) * 4)

__global__ __launch_bounds__(256)
void proj_out(const float* __restrict__ Wo, const float* __restrict__ bo,
              const float* __restrict__ addsrc, float* __restrict__ outp)
{
    extern __shared__ float psm[];
    float* As = psm;
    float* Ws = psm + 2 * 128 * 36;
    const uint32_t asB = (uint32_t)__cvta_generic_to_shared(As);
    const uint32_t wsB = (uint32_t)__cvta_generic_to_shared(Ws);

    const int tid = threadIdx.x;
    const int lane = tid & 31;
    const int g = lane >> 2, tig = lane & 3;
    const int wm = (tid >> 5) >> 1, wn = (tid >> 5) & 1;
    const int m0 = blockIdx.x * 128;
    const int c0 = blockIdx.y * 64;
    const int M = NQ * BATCH;

    float acc[2][4][4] = {};

    auto load_chunk = [&](int kc, int buf) {
        const int k0 = kc * 32;
        #pragma unroll
        for (int t = 0; t < 4; t++) {
            int i = tid + t * 256;
            int r = i >> 3, s = (i & 7) * 4;
            int row = m0 + r;
            uint32_t dst = asB + (((buf * 128 + r) * 36 + s) << 2);
            cpa16(dst, g_Oattn + (size_t)row * CDIM + k0 + s, row < M ? 16 : 0);
        }
        #pragma unroll
        for (int t = 0; t < 2; t++) {
            int i = tid + t * 256;
            int r = i >> 3, s = (i & 7) * 4;
            uint32_t dst = wsB + (((buf * 64 + r) * 36 + s) << 2);
            cpa16(dst, Wo + (size_t)(c0 + r) * CDIM + k0 + s, 16);
        }
    };
    auto compute = [&](int buf) {
        const float* Ab = As + buf * 128 * 36;
        const float* Wb = Ws + buf * 64 * 36;
        #pragma unroll
        for (int ks = 0; ks < 4; ks++) {
            uint32_t a[2][4], b[4][2];
            #pragma unroll
            for (int mt = 0; mt < 2; mt++) {
                int r = wm * 32 + mt * 16 + g;
                a[mt][0] = f2tf(Ab[r * 36 + ks * 8 + tig]);
                a[mt][1] = f2tf(Ab[(r + 8) * 36 + ks * 8 + tig]);
                a[mt][2] = f2tf(Ab[r * 36 + ks * 8 + tig + 4]);
                a[mt][3] = f2tf(Ab[(r + 8) * 36 + ks * 8 + tig + 4]);
            }
            #pragma unroll
            for (int nt = 0; nt < 4; nt++) {
                int c = wn * 32 + nt * 8 + g;
                b[nt][0] = f2tf(Wb[c * 36 + ks * 8 + tig]);
                b[nt][1] = f2tf(Wb[c * 36 + ks * 8 + tig + 4]);
            }
            #pragma unroll
            for (int mt = 0; mt < 2; mt++)
                #pragma unroll
                for (int nt = 0; nt < 4; nt++)
                    mma8(acc[mt][nt], a[mt], b[nt]);
        }
    };

    load_chunk(0, 0);
    CP_COMMIT; CP_WAIT0;
    __syncthreads();
    for (int kc = 0; kc < 8; kc++) {
        if (kc + 1 < 8) { load_chunk(kc + 1, (kc + 1) & 1); CP_COMMIT; }
        compute(kc & 1);
        if (kc + 1 < 8) { CP_WAIT0; __syncthreads(); }
    }

    #pragma unroll
    for (int mt = 0; mt < 2; mt++)
    #pragma unroll
    for (int nt = 0; nt < 4; nt++)
    #pragma unroll
    for (int cr = 0; cr < 4; cr++) {
        const int row = m0 + wm * 32 + mt * 16 + g + ((cr >= 2) ? 8 : 0);
        if (row >= M) continue;
        const int col = c0 + wn * 32 + nt * 8 + tig * 2 + (cr & 1);
        outp[(size_t)row * CDIM + col] =
            addsrc[(size_t)row * CDIM + col] + acc[mt][nt][cr] + bo[col];
    }
}

// ---------------------------------------------------------------------------
// bf16 flash attention — now 3 CTAs/SM (regs capped at 85).
// ---------------------------------------------------------------------------
#define ATT_Q_OFF   0
#define ATT_K_OFF   (64 * 96)
#define ATT_V_OFF   (ATT_K_OFF + 2 * 64 * 96)
#define ATT_SMEM_BYTES ((ATT_V_OFF + 2 * 32 * 96) * 2)     // 48 KB

__global__ __launch_bounds__(256, 3)
void attn_mma()
{
    extern __shared__ __nv_bfloat16 smb[];
    __nv_bfloat16* Qs = smb + ATT_Q_OFF;
    __nv_bfloat16* Ks = smb + ATT_K_OFF;
    __nv_bfloat16* Vs = smb + ATT_V_OFF;
    float* Os = (float*)Ks;
    float* Ml = (float*)Vs;
    const uint32_t qsB = (uint32_t)__cvta_generic_to_shared(Qs);
    const uint32_t ksB = (uint32_t)__cvta_generic_to_shared(Ks);
    const uint32_t vsB = (uint32_t)__cvta_generic_to_shared(Vs);

    const int tid = threadIdx.x;
    const int w = tid >> 5, lane = tid & 31;
    const int g = lane >> 2, tig = lane & 3;
    const int wm = w >> 1, wn = w & 1;
    const int bh = blockIdx.y;
    const int q0 = blockIdx.x * 64;

    auto issueQ = [&]() {
        #pragma unroll
        for (int t = 0; t < 2; t++) {
            int i = tid + t * 256;
            int r = i >> 3, c8 = i & 7;
            int n = q0 + r;
            uint32_t dst = qsB + (r * 96 + c8 * 8) * 2;
            cpa16(dst, &g_Qcat[((size_t)bh * NQ + (n < NQ ? n : 0)) * DQK + c8 * 8],
                  n < NQ ? 16 : 0);
        }
    };
    auto issueKV = [&](int kt, int buf) {
        const int mbase = kt * 64;
        #pragma unroll
        for (int t = 0; t < 2; t++) {
            int i = tid + t * 256;
            int r = i >> 3, c8 = i & 7;
            uint32_t dst = ksB + ((buf * 64 + r) * 96 + c8 * 8) * 2;
            cpa16(dst, &g_Kcat[((size_t)bh * NK + mbase + r) * DQK + c8 * 8], 16);
        }
        {
            int r = tid >> 3, c8 = tid & 7;
            uint32_t dst = vsB + ((buf * 32 + r) * 96 + c8 * 8) * 2;
            cpa16(dst, &g_Vh[((size_t)bh * DV + r) * NK + mbase + c8 * 8], 16);
        }
    };

    issueQ();
    issueKV(0, 0);
    CP_COMMIT;

    const __nv_bfloat16* kbase = Ks + (wn * 32 + g) * 96 + tig * 8;
    const __nv_bfloat16* vbase = Vs + g * 96 + wn * 32 + tig * 8;

    uint32_t qa[4][4];
    float oacc[4][4] = {};
    float m0 = -1e30f, m1 = -1e30f, l0 = 0.f, l1 = 0.f;

    CP_WAIT0;
    __syncthreads();

    {
        const int r = wm * 16 + g;
        #pragma unroll
        for (int p = 0; p < 2; p++) {
            uint4 ug  = *(const uint4*)(Qs + r * 96 + p * 32 + tig * 8);
            uint4 ug8 = *(const uint4*)(Qs + (r + 8) * 96 + p * 32 + tig * 8);
            qa[2*p][0]   = ug.x; qa[2*p][1]   = ug8.x;
            qa[2*p][2]   = ug.y; qa[2*p][3]   = ug8.y;
            qa[2*p+1][0] = ug.z; qa[2*p+1][1] = ug8.z;
            qa[2*p+1][2] = ug.w; qa[2*p+1][3] = ug8.w;
        }
    }

    const int NT = NK / 64;
    for (int kt = 0; kt < NT; kt++) {
        const int buf = kt & 1;
        if (kt + 1 < NT) { issueKV(kt + 1, buf ^ 1); CP_COMMIT; }

        const __nv_bfloat16* Kb = kbase + buf * (64 * 96);
        const __nv_bfloat16* Vb = vbase + buf * (32 * 96);

        float s[4][4];
        #pragma unroll
        for (int nt = 0; nt < 4; nt++) {
            uint4 kq0 = *(const uint4*)(Kb + nt * (8 * 96));
            uint4 kq1 = *(const uint4*)(Kb + nt * (8 * 96) + 32);
            s[nt][0] = s[nt][1] = s[nt][2] = s[nt][3] = 0.f;
            { uint32_t b[2] = {kq0.x, kq0.y}; mma16(s[nt], qa[0], b); }
            { uint32_t b[2] = {kq0.z, kq0.w}; mma16(s[nt], qa[1], b); }
            { uint32_t b[2] = {kq1.x, kq1.y}; mma16(s[nt], qa[2], b); }
            { uint32_t b[2] = {kq1.z, kq1.w}; mma16(s[nt], qa[3], b); }
        }

        float pm0 = -1e30f, pm1 = -1e30f;
        #pragma unroll
        for (int nt = 0; nt < 4; nt++) {
            pm0 = fmaxf(pm0, fmaxf(s[nt][0], s[nt][1]));
            pm1 = fmaxf(pm1, fmaxf(s[nt][2], s[nt][3]));
        }
        pm0 = fmaxf(pm0, __shfl_xor_sync(~0u, pm0, 1));
        pm0 = fmaxf(pm0, __shfl_xor_sync(~0u, pm0, 2));
        pm1 = fmaxf(pm1, __shfl_xor_sync(~0u, pm1, 1));
        pm1 = fmaxf(pm1, __shfl_xor_sync(~0u, pm1, 2));
        const float mn0 = fmaxf(m0, pm0), mn1 = fmaxf(m1, pm1);
        const float al0 = ex2(m0 - mn0), al1 = ex2(m1 - mn1);
        m0 = mn0; m1 = mn1;
        float ps0 = 0.f, ps1 = 0.f;
        #pragma unroll
        for (int nt = 0; nt < 4; nt++) {
            s[nt][0] = ex2(s[nt][0] - mn0);
            s[nt][1] = ex2(s[nt][1] - mn0);
            s[nt][2] = ex2(s[nt][2] - mn1);
            s[nt][3] = ex2(s[nt][3] - mn1);
            ps0 += s[nt][0] + s[nt][1];
            ps1 += s[nt][2] + s[nt][3];
        }
        ps0 += __shfl_xor_sync(~0u, ps0, 1); ps0 += __shfl_xor_sync(~0u, ps0, 2);
        ps1 += __shfl_xor_sync(~0u, ps1, 1); ps1 += __shfl_xor_sync(~0u, ps1, 2);
        l0 = l0 * al0 + ps0;
        l1 = l1 * al1 + ps1;
        #pragma unroll
        for (int nt = 0; nt < 4; nt++) {
            oacc[nt][0] *= al0; oacc[nt][1] *= al0;
            oacc[nt][2] *= al1; oacc[nt][3] *= al1;
        }

        uint4 vq[4];
        #pragma unroll
        for (int nt = 0; nt < 4; nt++)
            vq[nt] = *(const uint4*)(Vb + nt * (8 * 96));
        #pragma unroll
        for (int c = 0; c < 2; c++) {
            uint32_t a[4];
            a[0] = packbf(s[2*c][0],   s[2*c][1]);
            a[1] = packbf(s[2*c][2],   s[2*c][3]);
            a[2] = packbf(s[2*c+1][0], s[2*c+1][1]);
            a[3] = packbf(s[2*c+1][2], s[2*c+1][3]);
            #pragma unroll
            for (int nt = 0; nt < 4; nt++) {
                uint32_t b[2] = { c ? vq[nt].z : vq[nt].x,
                                  c ? vq[nt].w : vq[nt].y };
                mma16(oacc[nt], a, b);
            }
        }

        if (kt + 1 < NT) { CP_WAIT0; __syncthreads(); }
    }

    __syncthreads();

    const int r0 = wm * 16 + g;
    if (wn == 0) {
        #pragma unroll
        for (int nt = 0; nt < 4; nt++) {
            const int c = nt * 8 + tig * 2;
            Os[r0 * 36 + c]           = oacc[nt][0];
            Os[r0 * 36 + c + 1]       = oacc[nt][1];
            Os[(r0 + 8) * 36 + c]     = oacc[nt][2];
            Os[(r0 + 8) * 36 + c + 1] = oacc[nt][3];
        }
        if (tig == 0) {
            Ml[r0 * 4 + 0] = m0; Ml[r0 * 4 + 1] = l0;
            Ml[(r0 + 8) * 4 + 0] = m1; Ml[(r0 + 8) * 4 + 1] = l1;
        }
    }
    __syncthreads();
    if (wn == 1) {
        const int b = bh >> 3, h = bh & 7;
        const float mo0 = Ml[r0 * 4 + 0], lo0 = Ml[r0 * 4 + 1];
        const float mo1 = Ml[(r0 + 8) * 4 + 0], lo1 = Ml[(r0 + 8) * 4 + 1];
        const float mg0 = fmaxf(mo0, m0), mg1 = fmaxf(mo1, m1);
        const float so0 = ex2(mo0 - mg0), sw0 = ex2(m0 - mg0);
        const float so1 = ex2(mo1 - mg1), sw1 = ex2(m1 - mg1);
        const float inv0 = 1.f / (lo0 * so0 + l0 * sw0);
        const float inv1 = 1.f / (lo1 * so1 + l1 * sw1);
        const int n0 = q0 + r0, n1 = n0 + 8;
        #pragma unroll
        for (int nt = 0; nt < 4; nt++) {
            const int c = nt * 8 + tig * 2;
            if (n0 < NQ) {
                const size_t base = ((size_t)n0 * BATCH + b) * CDIM + h * DV + c;
                g_Oattn[base]     = (Os[r0 * 36 + c]     * so0 + oacc[nt][0] * sw0) * inv0;
                g_Oattn[base + 1] = (Os[r0 * 36 + c + 1] * so0 + oacc[nt][1] * sw0) * inv0;
            }
            if (n1 < NQ) {
                const size_t base = ((size_t)n1 * BATCH + b) * CDIM + h * DV + c;
                g_Oattn[base]     = (Os[(r0 + 8) * 36 + c]     * so1 + oacc[nt][2] * sw1) * inv1;
                g_Oattn[base + 1] = (Os[(r0 + 8) * 36 + c + 1] * so1 + oacc[nt][3] * sw1) * inv1;
            }
        }
    }
}

// ---------------------------------------------------------------------------
extern "C" void kernel_launch(void* const* d_in, const int* in_sizes, int n_in,
                              void* d_out, int out_size)
{
    const float* query    = (const float*)d_in[0];
    const float* key      = (const float*)d_in[1];
    const float* value    = (const float*)d_in[2];
    const float* querypos = (const float*)d_in[3];
    const float* keypos   = (const float*)d_in[4];
    const float* qsine    = (const float*)d_in[5];
    const float* Wqc = (const float*)d_in[6];  const float* bqc = (const float*)d_in[7];
    const float* Wqp = (const float*)d_in[8];  const float* bqp = (const float*)d_in[9];
    const float* Wqs = (const float*)d_in[10]; const float* bqs = (const float*)d_in[11];
    const float* Wkc = (const float*)d_in[12]; const float* bkc = (const float*)d_in[13];
    const float* Wkp = (const float*)d_in[14]; const float* bkp = (const float*)d_in[15];
    const float* Wv  = (const float*)d_in[16]; const float* bv  = (const float*)d_in[17];
    const float* Wo  = (const float*)d_in[18]; const float* bo  = (const float*)d_in[19];
    float* out = (float*)d_out;

    static bool attr_done = false;
    if (!attr_done) {
        cudaFuncSetAttribute(proj_out, cudaFuncAttributeMaxDynamicSharedMemorySize, PROJ_SMEM);
        cudaFuncSetAttribute(attn_mma, cudaFuncAttributeMaxDynamicSharedMemorySize, ATT_SMEM_BYTES);
        attr_done = true;
    }

    wconv<<<384, 256>>>(Wkc, Wkp, Wv, Wqc, Wqp, Wqs);
    proj_fused<<<1140, 256, PROJB_SMEM>>>(key, keypos, value, query, querypos, qsine,
                                          bkc, bkp, bv, bqc, bqp, bqs);
    attn_mma<<<dim3((NQ + 63) / 64, 32), 256, ATT_SMEM_BYTES>>>();
    proj_out<<<dim3(29, 4), 256, PROJ_SMEM>>>(Wo, bo, query, out);
}